// round 1
// baseline (speedup 1.0000x reference)
#include <cuda_runtime.h>
#include <math.h>

// Problem constants
#define BB   16
#define TT   256
#define VV   25
#define DM   128
#define HH   8
#define HD   16
#define MAXT 300
#define SEQS (BB*VV)          // 400
#define NTOK (SEQS*TT)        // 102400
#define NBIAS (2*MAXT-1)      // 599

// ---------------- scratch (device globals; no runtime allocation) -------------
__device__ float g_xn  [NTOK*DM];     // LN1 output
__device__ float g_qkv [NTOK*3*DM];   // qkv projections
__device__ float g_attn[NTOK*DM];     // attention output (token-major, h*d inner)
__device__ float g_xf  [NTOK*DM];     // after proj + residual
__device__ float g_z   [NTOK*DM];     // LN2 output
__device__ float g_h   [NTOK*4*DM];   // FFN hidden

// ---------------- LayerNorm (optionally gathering from (B,T,V,D) input) -------
template<bool GATHER>
__global__ void ln_kernel(const float* __restrict__ in,
                          const float* __restrict__ gw,
                          const float* __restrict__ bw,
                          float* __restrict__ out)
{
    int m   = blockIdx.x;          // token row 0..NTOK-1, m = (b*V+v)*T + t
    int tid = threadIdx.x;         // 128 threads, one element each
    const float* src;
    if (GATHER) {
        int seq = m / TT, t = m % TT;
        int b = seq / VV, v = seq % VV;
        src = in + ((b*TT + t)*VV + v) * DM;
    } else {
        src = in + m * DM;
    }
    float x = src[tid];

    __shared__ float red1[4], red2[4];
    float s = x;
    #pragma unroll
    for (int o = 16; o > 0; o >>= 1) s += __shfl_down_sync(0xffffffffu, s, o);
    if ((tid & 31) == 0) red1[tid >> 5] = s;
    __syncthreads();
    float mean = (red1[0] + red1[1] + red1[2] + red1[3]) * (1.0f / DM);

    float dx = x - mean;
    float s2 = dx * dx;
    #pragma unroll
    for (int o = 16; o > 0; o >>= 1) s2 += __shfl_down_sync(0xffffffffu, s2, o);
    if ((tid & 31) == 0) red2[tid >> 5] = s2;
    __syncthreads();
    float var = (red2[0] + red2[1] + red2[2] + red2[3]) * (1.0f / DM);

    out[m * DM + tid] = dx * rsqrtf(var + 1e-5f) * gw[tid] + bw[tid];
}

// ---------------- Tiled SGEMM: C[M,N] = A[M,K] @ B[K,N] + epilogue -------------
// EPI 0: + bias                              -> C
// EPI 1: + bias + gather(x original layout)  -> C            (proj + residual)
// EPI 2: gelu_exact(+ bias)                  -> C            (FFN1)
// EPI 3: + bias + extra[row]                 -> scatter to (B,T,V,D) output
template<int KDIM, int EPI>
__global__ void gemm_kernel(const float* __restrict__ A,
                            const float* __restrict__ B,
                            const float* __restrict__ bias,
                            const float* __restrict__ extra,
                            float* __restrict__ C, int N)
{
    __shared__ float As[16][65];   // padded: transposed A tile
    __shared__ float Bs[16][64];

    const int bx  = blockIdx.x, by = blockIdx.y;
    const int tid = threadIdx.x;             // 256
    const int tx  = tid & 15, ty = tid >> 4; // 16x16 thread grid, 4x4 each

    const int arow  = tid >> 2;              // 0..63
    const int acol4 = (tid & 3) * 4;         // 0,4,8,12
    const int brow  = tid >> 4;              // 0..15
    const int bcol4 = (tid & 15) * 4;

    const float* Ab = A + (by * 64) * KDIM;
    const float* Bb = B + bx * 64;

    float acc[4][4] = {};

    for (int kt = 0; kt < KDIM; kt += 16) {
        float4 av = *(const float4*)(Ab + arow * KDIM + kt + acol4);
        As[acol4 + 0][arow] = av.x;
        As[acol4 + 1][arow] = av.y;
        As[acol4 + 2][arow] = av.z;
        As[acol4 + 3][arow] = av.w;
        *(float4*)&Bs[brow][bcol4] = *(const float4*)(Bb + (kt + brow) * N + bcol4);
        __syncthreads();

        #pragma unroll
        for (int k = 0; k < 16; k++) {
            float a0 = As[k][ty*4+0], a1 = As[k][ty*4+1];
            float a2 = As[k][ty*4+2], a3 = As[k][ty*4+3];
            float4 b4 = *(const float4*)&Bs[k][tx*4];
            acc[0][0] += a0*b4.x; acc[0][1] += a0*b4.y; acc[0][2] += a0*b4.z; acc[0][3] += a0*b4.w;
            acc[1][0] += a1*b4.x; acc[1][1] += a1*b4.y; acc[1][2] += a1*b4.z; acc[1][3] += a1*b4.w;
            acc[2][0] += a2*b4.x; acc[2][1] += a2*b4.y; acc[2][2] += a2*b4.z; acc[2][3] += a2*b4.w;
            acc[3][0] += a3*b4.x; acc[3][1] += a3*b4.y; acc[3][2] += a3*b4.z; acc[3][3] += a3*b4.w;
        }
        __syncthreads();
    }

    const int colb = bx * 64 + tx * 4;
    float4 bv = *(const float4*)&bias[colb];

    #pragma unroll
    for (int i = 0; i < 4; i++) {
        int row = by * 64 + ty * 4 + i;
        float4 r;
        r.x = acc[i][0] + bv.x;
        r.y = acc[i][1] + bv.y;
        r.z = acc[i][2] + bv.z;
        r.w = acc[i][3] + bv.w;

        if (EPI == 1 || EPI == 3) {
            // gathered layout offset for token row -> (B,T,V,D)
            int seq = row / TT, t = row % TT;
            int b = seq / VV, v = seq % VV;
            int goff = ((b*TT + t)*VV + v) * DM + colb;
            if (EPI == 1) {
                float4 e = *(const float4*)&extra[goff];
                r.x += e.x; r.y += e.y; r.z += e.z; r.w += e.w;
                *(float4*)&C[row * N + colb] = r;
            } else {
                float4 e = *(const float4*)&extra[row * DM + colb];
                r.x += e.x; r.y += e.y; r.z += e.z; r.w += e.w;
                *(float4*)&C[goff] = r;
            }
        } else if (EPI == 2) {
            r.x = 0.5f * r.x * (1.0f + erff(r.x * 0.70710678118654752f));
            r.y = 0.5f * r.y * (1.0f + erff(r.y * 0.70710678118654752f));
            r.z = 0.5f * r.z * (1.0f + erff(r.z * 0.70710678118654752f));
            r.w = 0.5f * r.w * (1.0f + erff(r.w * 0.70710678118654752f));
            *(float4*)&C[row * N + colb] = r;
        } else {
            *(float4*)&C[row * N + colb] = r;
        }
    }
}

// ---------------- Attention: one block per (seq, head), flash-style ----------
__global__ void attn_kernel(const float* __restrict__ qkv,
                            const float* __restrict__ logit_scale,
                            const float* __restrict__ rpb,
                            float* __restrict__ out)
{
    const int seq = blockIdx.x;
    const int h   = blockIdx.y;
    const int t   = threadIdx.x;   // 256: one query row per thread

    __shared__ float Ks[TT][HD];
    __shared__ float Vs[TT][HD];
    __shared__ float bs[NBIAS + 1];

    for (int i = t; i < NBIAS; i += TT) bs[i] = rpb[h * NBIAS + i];

    const float* base = qkv + (seq * TT + t) * (3 * DM) + h * HD;

    // load q, k, v rows for this token
    float q[HD], kv[HD];
    #pragma unroll
    for (int i = 0; i < HD; i += 4) {
        float4 f = *(const float4*)(base + i);
        q[i] = f.x; q[i+1] = f.y; q[i+2] = f.z; q[i+3] = f.w;
    }
    #pragma unroll
    for (int i = 0; i < HD; i += 4) {
        float4 f = *(const float4*)(base + DM + i);
        kv[i] = f.x; kv[i+1] = f.y; kv[i+2] = f.z; kv[i+3] = f.w;
    }
    float kss = 0.f;
    #pragma unroll
    for (int i = 0; i < HD; i++) kss += kv[i] * kv[i];
    float kinv = 1.0f / fmaxf(sqrtf(kss), 1e-12f);
    #pragma unroll
    for (int i = 0; i < HD; i += 4) {
        float4 f; f.x = kv[i]*kinv; f.y = kv[i+1]*kinv; f.z = kv[i+2]*kinv; f.w = kv[i+3]*kinv;
        *(float4*)&Ks[t][i] = f;
    }
    #pragma unroll
    for (int i = 0; i < HD; i += 4) {
        *(float4*)&Vs[t][i] = *(const float4*)(base + 2 * DM + i);
    }

    // normalize q, fold in scale / sqrt(d)
    float ls    = logit_scale[h];
    float scale = __expf(fminf(ls, 4.6051701859880914f));   // log(100)
    float qss = 0.f;
    #pragma unroll
    for (int i = 0; i < HD; i++) qss += q[i] * q[i];
    float qf = scale * 0.25f / fmaxf(sqrtf(qss), 1e-12f);   // /sqrt(16)=*0.25
    #pragma unroll
    for (int i = 0; i < HD; i++) q[i] *= qf;

    __syncthreads();

    float mrun = -1e30f, l = 0.f, o[HD] = {};
    #pragma unroll 4
    for (int s = 0; s < TT; s++) {
        float dot = 0.f;
        #pragma unroll
        for (int i = 0; i < HD; i++) dot += q[i] * Ks[s][i];
        float sc = dot + bs[t - s + (MAXT - 1)];
        float mn = fmaxf(mrun, sc);
        float c  = __expf(mrun - mn);
        float p  = __expf(sc - mn);
        l = l * c + p;
        #pragma unroll
        for (int i = 0; i < HD; i++) o[i] = o[i] * c + p * Vs[s][i];
        mrun = mn;
    }
    float il = 1.0f / l;
    float* dst = out + (seq * TT + t) * DM + h * HD;
    #pragma unroll
    for (int i = 0; i < HD; i += 4) {
        float4 f; f.x = o[i]*il; f.y = o[i+1]*il; f.z = o[i+2]*il; f.w = o[i+3]*il;
        *(float4*)&dst[i] = f;
    }
}

// -------------------------------- launch --------------------------------------
extern "C" void kernel_launch(void* const* d_in, const int* in_sizes, int n_in,
                              void* d_out, int out_size)
{
    const float* x     = (const float*)d_in[0];
    const float* ln1g  = (const float*)d_in[1];
    const float* ln1b  = (const float*)d_in[2];
    const float* qkvw  = (const float*)d_in[3];
    const float* qkvb  = (const float*)d_in[4];
    const float* projw = (const float*)d_in[5];
    const float* projb = (const float*)d_in[6];
    const float* ls    = (const float*)d_in[7];
    const float* rpb   = (const float*)d_in[8];
    const float* ln2g  = (const float*)d_in[9];
    const float* ln2b  = (const float*)d_in[10];
    const float* w1    = (const float*)d_in[11];
    const float* b1    = (const float*)d_in[12];
    const float* w2    = (const float*)d_in[13];
    const float* b2    = (const float*)d_in[14];
    float* out = (float*)d_out;

    float *xn, *qkv, *attn, *xf, *z, *hb;
    cudaGetSymbolAddress((void**)&xn,   g_xn);
    cudaGetSymbolAddress((void**)&qkv,  g_qkv);
    cudaGetSymbolAddress((void**)&attn, g_attn);
    cudaGetSymbolAddress((void**)&xf,   g_xf);
    cudaGetSymbolAddress((void**)&z,    g_z);
    cudaGetSymbolAddress((void**)&hb,   g_h);

    // 1) gather + LN1
    ln_kernel<true><<<NTOK, 128>>>(x, ln1g, ln1b, xn);
    // 2) QKV projection (M=102400, N=384, K=128)
    gemm_kernel<128, 0><<<dim3(384/64, NTOK/64), 256>>>(xn, qkvw, qkvb, nullptr, qkv, 384);
    // 3) attention per (seq, head)
    attn_kernel<<<dim3(SEQS, HH), TT>>>(qkv, ls, rpb, attn);
    // 4) proj + residual (gathered x)
    gemm_kernel<128, 1><<<dim3(128/64, NTOK/64), 256>>>(attn, projw, projb, x, xf, 128);
    // 5) LN2
    ln_kernel<false><<<NTOK, 128>>>(xf, ln2g, ln2b, z);
    // 6) FFN1 + exact GELU (N=512, K=128)
    gemm_kernel<128, 2><<<dim3(512/64, NTOK/64), 256>>>(z, w1, b1, nullptr, hb, 512);
    // 7) FFN2 + residual, scattered to (B,T,V,D) output (K=512)
    gemm_kernel<512, 3><<<dim3(128/64, NTOK/64), 256>>>(hb, w2, b2, xf, out, 128);
}

// round 2
// speedup vs baseline: 1.8150x; 1.8150x over previous
#include <cuda_runtime.h>
#include <math.h>
#include <stdint.h>

// Problem constants
#define BB   16
#define TT   256
#define VV   25
#define DM   128
#define HH   8
#define HD   16
#define MAXT 300
#define SEQS (BB*VV)          // 400
#define NTOK (SEQS*TT)        // 102400
#define NBIAS (2*MAXT-1)      // 599

// GEMM tiling
#define BM 128
#define BN 128
#define BK 32
#define AS_STRIDE (BK + 4)    // 36 floats  (bank = 4g+tig : conflict-free)
#define BS_STRIDE (BN + 8)    // 136 floats (bank = 8tig+g : conflict-free)
#define BOFF (2*BM*AS_STRIDE) // float offset of B tiles in smem
#define GEMM_SMEM ((2*BM*AS_STRIDE + 2*BK*BS_STRIDE)*4)   // 71680 bytes

// ---------------- scratch (device globals; no runtime allocation) -------------
__device__ float g_xn  [NTOK*DM];     // LN1 output
__device__ float g_qkv [NTOK*3*DM];   // qkv projections
__device__ float g_attn[NTOK*DM];     // attention output
__device__ float g_xf  [NTOK*DM];     // after proj + residual
__device__ float g_z   [NTOK*DM];     // LN2 output
__device__ float g_h   [NTOK*4*DM];   // FFN hidden

// ---------------- small helpers -----------------------------------------------
__device__ __forceinline__ uint32_t f2tf(float v) {
    uint32_t r;
    asm("cvt.rna.tf32.f32 %0, %1;" : "=r"(r) : "f"(v));
    return r;
}
__device__ __forceinline__ void mma8(float* c, const uint32_t* a, const uint32_t* b) {
    asm volatile(
        "mma.sync.aligned.m16n8k8.row.col.f32.tf32.tf32.f32 "
        "{%0,%1,%2,%3}, {%4,%5,%6,%7}, {%8,%9}, {%0,%1,%2,%3};"
        : "+f"(c[0]), "+f"(c[1]), "+f"(c[2]), "+f"(c[3])
        : "r"(a[0]), "r"(a[1]), "r"(a[2]), "r"(a[3]), "r"(b[0]), "r"(b[1]));
}
__device__ __forceinline__ void cp16(uint32_t dst, const float* src) {
    asm volatile("cp.async.cg.shared.global [%0], [%1], 16;" :: "r"(dst), "l"(src));
}
__device__ __forceinline__ void cp_commit() {
    asm volatile("cp.async.commit_group;" ::: "memory");
}
template<int N>
__device__ __forceinline__ void cp_wait() {
    asm volatile("cp.async.wait_group %0;" :: "n"(N) : "memory");
}
__device__ __forceinline__ int gather_off(int row) {
    int seq = row / TT, t = row % TT;
    int b = seq / VV, v = seq % VV;
    return ((b*TT + t)*VV + v) * DM;
}

// ---------------- LayerNorm (optionally gathering from (B,T,V,D) input) -------
template<bool GATHER>
__global__ void ln_kernel(const float* __restrict__ in,
                          const float* __restrict__ gw,
                          const float* __restrict__ bw,
                          float* __restrict__ out)
{
    int m   = blockIdx.x;
    int tid = threadIdx.x;         // 128 threads
    const float* src;
    if (GATHER) {
        int seq = m / TT, t = m % TT;
        int b = seq / VV, v = seq % VV;
        src = in + ((b*TT + t)*VV + v) * DM;
    } else {
        src = in + m * DM;
    }
    float x = src[tid];

    __shared__ float red1[4], red2[4];
    float s = x;
    #pragma unroll
    for (int o = 16; o > 0; o >>= 1) s += __shfl_down_sync(0xffffffffu, s, o);
    if ((tid & 31) == 0) red1[tid >> 5] = s;
    __syncthreads();
    float mean = (red1[0] + red1[1] + red1[2] + red1[3]) * (1.0f / DM);

    float dx = x - mean;
    float s2 = dx * dx;
    #pragma unroll
    for (int o = 16; o > 0; o >>= 1) s2 += __shfl_down_sync(0xffffffffu, s2, o);
    if ((tid & 31) == 0) red2[tid >> 5] = s2;
    __syncthreads();
    float var = (red2[0] + red2[1] + red2[2] + red2[3]) * (1.0f / DM);

    out[m * DM + tid] = dx * rsqrtf(var + 1e-5f) * gw[tid] + bw[tid];
}

// ---------------- tf32 tensor-core GEMM ---------------------------------------
// C[M,N] = A[M,K] @ B[K,N] + epilogue
// EPI 0: + bias                              -> C
// EPI 1: + bias + gather(x original layout)  -> C            (proj + residual)
// EPI 2: gelu_exact(+ bias)                  -> C            (FFN1)
// EPI 3: + bias + extra[row]                 -> scatter to (B,T,V,D) output
template<int KDIM, int NDIM, int EPI>
__global__ void __launch_bounds__(256, 2)
mma_gemm(const float* __restrict__ A,
         const float* __restrict__ B,
         const float* __restrict__ bias,
         const float* __restrict__ extra,
         float* __restrict__ C)
{
    extern __shared__ float smem[];
    float* As = smem;          // [2][BM][AS_STRIDE]
    float* Bs = smem + BOFF;   // [2][BK][BS_STRIDE]
    uint32_t sbase = (uint32_t)__cvta_generic_to_shared(smem);

    const int tid  = threadIdx.x;
    const int bx   = blockIdx.x, by = blockIdx.y;
    const int lane = tid & 31, warp = tid >> 5;
    const int wm   = (warp & 1) * 64;     // 2 warps along M (64 rows each)
    const int wn   = (warp >> 1) * 32;    // 4 warps along N (32 cols each)
    const int g    = lane >> 2, tig = lane & 3;

    // global load mapping
    const int a_r = tid >> 3, a_k = (tid & 7) * 4;     // + c*32 rows
    const int b_r = tid >> 5, b_n = (tid & 31) * 4;    // + c*8 rows
    const float* Ag = A + (long)(by*BM + a_r) * KDIM + a_k;
    const float* Bg = B + (long)b_r * NDIM + bx*BN + b_n;

    const int NK = KDIM / BK;
    float acc[4][4][4] = {};

    auto load_tile = [&](int kt, int s) {
        #pragma unroll
        for (int c = 0; c < 4; c++) {
            int off = (s*BM + c*32 + a_r) * AS_STRIDE + a_k;
            cp16(sbase + 4*off, Ag + (long)c*32*KDIM + kt*BK);
        }
        #pragma unroll
        for (int c = 0; c < 4; c++) {
            int off = BOFF + (s*BK + c*8 + b_r) * BS_STRIDE + b_n;
            cp16(sbase + 4*off, Bg + (long)(kt*BK + c*8) * NDIM);
        }
    };

    load_tile(0, 0);
    cp_commit();

    #pragma unroll 1
    for (int kt = 0; kt < NK; kt++) {
        if (kt + 1 < NK) {
            load_tile(kt + 1, (kt + 1) & 1);
            cp_commit();
            cp_wait<1>();
        } else {
            cp_wait<0>();
        }
        __syncthreads();

        const int s = kt & 1;
        #pragma unroll
        for (int ks = 0; ks < BK; ks += 8) {
            uint32_t af[4][4], bf[4][2];
            #pragma unroll
            for (int mi = 0; mi < 4; mi++) {
                int r0 = (s*BM + wm + mi*16 + g) * AS_STRIDE;
                af[mi][0] = f2tf(As[r0              + ks + tig]);
                af[mi][1] = f2tf(As[r0 + 8*AS_STRIDE + ks + tig]);
                af[mi][2] = f2tf(As[r0              + ks + tig + 4]);
                af[mi][3] = f2tf(As[r0 + 8*AS_STRIDE + ks + tig + 4]);
            }
            #pragma unroll
            for (int ni = 0; ni < 4; ni++) {
                int cc = wn + ni*8 + g;
                bf[ni][0] = f2tf(Bs[(s*BK + ks + tig    ) * BS_STRIDE + cc]);
                bf[ni][1] = f2tf(Bs[(s*BK + ks + tig + 4) * BS_STRIDE + cc]);
            }
            #pragma unroll
            for (int mi = 0; mi < 4; mi++)
                #pragma unroll
                for (int ni = 0; ni < 4; ni++)
                    mma8(acc[mi][ni], af[mi], bf[ni]);
        }
        __syncthreads();
    }

    // ---------------- epilogue ----------------
    #pragma unroll
    for (int mi = 0; mi < 4; mi++) {
        #pragma unroll
        for (int rr = 0; rr < 2; rr++) {
            int row = by*BM + wm + mi*16 + rr*8 + g;
            int go = 0;
            if (EPI == 1 || EPI == 3) go = gather_off(row);
            #pragma unroll
            for (int ni = 0; ni < 4; ni++) {
                int col = bx*BN + wn + ni*8 + 2*tig;
                float vx = acc[mi][ni][rr*2 + 0] + bias[col];
                float vy = acc[mi][ni][rr*2 + 1] + bias[col + 1];
                if (EPI == 0) {
                    float2 r = {vx, vy};
                    *(float2*)&C[(long)row*NDIM + col] = r;
                } else if (EPI == 1) {
                    vx += extra[go + col];
                    vy += extra[go + col + 1];
                    float2 r = {vx, vy};
                    *(float2*)&C[(long)row*NDIM + col] = r;
                } else if (EPI == 2) {
                    vx = 0.5f * vx * (1.0f + erff(vx * 0.70710678118654752f));
                    vy = 0.5f * vy * (1.0f + erff(vy * 0.70710678118654752f));
                    float2 r = {vx, vy};
                    *(float2*)&C[(long)row*NDIM + col] = r;
                } else {  // EPI 3
                    vx += extra[(long)row*DM + col];
                    vy += extra[(long)row*DM + col + 1];
                    float2 r = {vx, vy};
                    *(float2*)&C[go + col] = r;
                }
            }
        }
    }
}

// ---------------- Attention: one block per (seq, head), flash-style ----------
__global__ void attn_kernel(const float* __restrict__ qkv,
                            const float* __restrict__ logit_scale,
                            const float* __restrict__ rpb,
                            float* __restrict__ out)
{
    const int seq = blockIdx.x;
    const int h   = blockIdx.y;
    const int t   = threadIdx.x;   // 256: one query row per thread

    __shared__ float Ks[TT][HD];
    __shared__ float Vs[TT][HD];
    __shared__ float bs[NBIAS + 1];

    for (int i = t; i < NBIAS; i += TT) bs[i] = rpb[h * NBIAS + i];

    const float* base = qkv + (long)(seq * TT + t) * (3 * DM) + h * HD;

    float q[HD], kv[HD];
    #pragma unroll
    for (int i = 0; i < HD; i += 4) {
        float4 f = *(const float4*)(base + i);
        q[i] = f.x; q[i+1] = f.y; q[i+2] = f.z; q[i+3] = f.w;
    }
    #pragma unroll
    for (int i = 0; i < HD; i += 4) {
        float4 f = *(const float4*)(base + DM + i);
        kv[i] = f.x; kv[i+1] = f.y; kv[i+2] = f.z; kv[i+3] = f.w;
    }
    float kss = 0.f;
    #pragma unroll
    for (int i = 0; i < HD; i++) kss += kv[i] * kv[i];
    float kinv = 1.0f / fmaxf(sqrtf(kss), 1e-12f);
    #pragma unroll
    for (int i = 0; i < HD; i += 4) {
        float4 f; f.x = kv[i]*kinv; f.y = kv[i+1]*kinv; f.z = kv[i+2]*kinv; f.w = kv[i+3]*kinv;
        *(float4*)&Ks[t][i] = f;
    }
    #pragma unroll
    for (int i = 0; i < HD; i += 4) {
        *(float4*)&Vs[t][i] = *(const float4*)(base + 2 * DM + i);
    }

    float ls    = logit_scale[h];
    float scale = __expf(fminf(ls, 4.6051701859880914f));   // log(100)
    float qss = 0.f;
    #pragma unroll
    for (int i = 0; i < HD; i++) qss += q[i] * q[i];
    float qf = scale * 0.25f / fmaxf(sqrtf(qss), 1e-12f);
    #pragma unroll
    for (int i = 0; i < HD; i++) q[i] *= qf;

    __syncthreads();

    float mrun = -1e30f, l = 0.f, o[HD] = {};
    #pragma unroll 4
    for (int s = 0; s < TT; s++) {
        float dot = 0.f;
        #pragma unroll
        for (int i = 0; i < HD; i++) dot += q[i] * Ks[s][i];
        float sc = dot + bs[t - s + (MAXT - 1)];
        float mn = fmaxf(mrun, sc);
        float c  = __expf(mrun - mn);
        float p  = __expf(sc - mn);
        l = l * c + p;
        #pragma unroll
        for (int i = 0; i < HD; i++) o[i] = o[i] * c + p * Vs[s][i];
        mrun = mn;
    }
    float il = 1.0f / l;
    float* dst = out + (long)(seq * TT + t) * DM + h * HD;
    #pragma unroll
    for (int i = 0; i < HD; i += 4) {
        float4 f; f.x = o[i]*il; f.y = o[i+1]*il; f.z = o[i+2]*il; f.w = o[i+3]*il;
        *(float4*)&dst[i] = f;
    }
}

// -------------------------------- launch --------------------------------------
extern "C" void kernel_launch(void* const* d_in, const int* in_sizes, int n_in,
                              void* d_out, int out_size)
{
    const float* x     = (const float*)d_in[0];
    const float* ln1g  = (const float*)d_in[1];
    const float* ln1b  = (const float*)d_in[2];
    const float* qkvw  = (const float*)d_in[3];
    const float* qkvb  = (const float*)d_in[4];
    const float* projw = (const float*)d_in[5];
    const float* projb = (const float*)d_in[6];
    const float* ls    = (const float*)d_in[7];
    const float* rpb   = (const float*)d_in[8];
    const float* ln2g  = (const float*)d_in[9];
    const float* ln2b  = (const float*)d_in[10];
    const float* w1    = (const float*)d_in[11];
    const float* b1    = (const float*)d_in[12];
    const float* w2    = (const float*)d_in[13];
    const float* b2    = (const float*)d_in[14];
    float* out = (float*)d_out;

    float *xn, *qkv, *attn, *xf, *z, *hb;
    cudaGetSymbolAddress((void**)&xn,   g_xn);
    cudaGetSymbolAddress((void**)&qkv,  g_qkv);
    cudaGetSymbolAddress((void**)&attn, g_attn);
    cudaGetSymbolAddress((void**)&xf,   g_xf);
    cudaGetSymbolAddress((void**)&z,    g_z);
    cudaGetSymbolAddress((void**)&hb,   g_h);

    // allow >48KB dynamic smem for the GEMM kernels (no-op after first call)
    cudaFuncSetAttribute(mma_gemm<128, 384, 0>, cudaFuncAttributeMaxDynamicSharedMemorySize, GEMM_SMEM);
    cudaFuncSetAttribute(mma_gemm<128, 128, 1>, cudaFuncAttributeMaxDynamicSharedMemorySize, GEMM_SMEM);
    cudaFuncSetAttribute(mma_gemm<128, 512, 2>, cudaFuncAttributeMaxDynamicSharedMemorySize, GEMM_SMEM);
    cudaFuncSetAttribute(mma_gemm<512, 128, 3>, cudaFuncAttributeMaxDynamicSharedMemorySize, GEMM_SMEM);

    // 1) gather + LN1
    ln_kernel<true><<<NTOK, 128>>>(x, ln1g, ln1b, xn);
    // 2) QKV projection (M=102400, N=384, K=128)
    mma_gemm<128, 384, 0><<<dim3(384/BN, NTOK/BM), 256, GEMM_SMEM>>>(xn, qkvw, qkvb, nullptr, qkv);
    // 3) attention per (seq, head)
    attn_kernel<<<dim3(SEQS, HH), TT>>>(qkv, ls, rpb, attn);
    // 4) proj + residual (gathered x)
    mma_gemm<128, 128, 1><<<dim3(128/BN, NTOK/BM), 256, GEMM_SMEM>>>(attn, projw, projb, x, xf);
    // 5) LN2
    ln_kernel<false><<<NTOK, 128>>>(xf, ln2g, ln2b, z);
    // 6) FFN1 + exact GELU (N=512, K=128)
    mma_gemm<128, 512, 2><<<dim3(512/BN, NTOK/BM), 256, GEMM_SMEM>>>(z, w1, b1, nullptr, hb);
    // 7) FFN2 + residual, scattered to (B,T,V,D) output (K=512)
    mma_gemm<512, 128, 3><<<dim3(128/BN, NTOK/BM), 256, GEMM_SMEM>>>(hb, w2, b2, xf, out);
}

// round 3
// speedup vs baseline: 1.9780x; 1.0898x over previous
#include <cuda_runtime.h>
#include <math.h>
#include <stdint.h>

// Problem constants
#define BB   16
#define TT   256
#define VV   25
#define DM   128
#define HH   8
#define HD   16
#define MAXT 300
#define SEQS (BB*VV)          // 400
#define NTOK (SEQS*TT)        // 102400
#define NBIAS (2*MAXT-1)      // 599
#define PART (HH*NTOK*HD)     // per q/k/v head-major part size

// GEMM tiling
#define BM 128
#define BN 128
#define BK 32
#define AS_STRIDE (BK + 4)    // 36 floats  (bank = 4g+tig : conflict-free)
#define BS_STRIDE (BN + 8)    // 136 floats (bank = 8tig+g : conflict-free)
#define BOFF (2*BM*AS_STRIDE) // float offset of B tiles in smem
#define GEMM_SMEM ((2*BM*AS_STRIDE + 2*BK*BS_STRIDE)*4)   // 71680 bytes

// weight-prep segment offsets (tf32-rounded copies)
#define WOFF_QKV  0
#define WOFF_PROJ 49152
#define WOFF_W1   65536
#define WOFF_W2   131072
#define WTOTAL    196608

// ---------------- scratch (device globals; no runtime allocation) -------------
__device__ float g_xn  [NTOK*DM];     // LN1 output (tf32-rounded)
__device__ float g_qkv [NTOK*3*DM];   // q/k/v, head-major [3][H][NTOK][16]
__device__ float g_attn[NTOK*DM];     // attention output, head-major (tf32)
__device__ float g_xf  [NTOK*DM];     // after proj + residual (fp32)
__device__ float g_z   [NTOK*DM];     // LN2 output (tf32-rounded)
__device__ float g_h   [NTOK*4*DM];   // FFN hidden (tf32-rounded)
__device__ float g_w   [WTOTAL];      // tf32-rounded weights

// ---------------- small helpers -----------------------------------------------
__device__ __forceinline__ uint32_t f2tf(float v) {
    uint32_t r;
    asm("cvt.rna.tf32.f32 %0, %1;" : "=r"(r) : "f"(v));
    return r;
}
__device__ __forceinline__ float f2tff(float v) { return __uint_as_float(f2tf(v)); }

__device__ __forceinline__ void mma8(float* c, const uint32_t* a, const uint32_t* b) {
    asm volatile(
        "mma.sync.aligned.m16n8k8.row.col.f32.tf32.tf32.f32 "
        "{%0,%1,%2,%3}, {%4,%5,%6,%7}, {%8,%9}, {%0,%1,%2,%3};"
        : "+f"(c[0]), "+f"(c[1]), "+f"(c[2]), "+f"(c[3])
        : "r"(a[0]), "r"(a[1]), "r"(a[2]), "r"(a[3]), "r"(b[0]), "r"(b[1]));
}
__device__ __forceinline__ void cp16(uint32_t dst, const float* src) {
    asm volatile("cp.async.cg.shared.global [%0], [%1], 16;" :: "r"(dst), "l"(src));
}
__device__ __forceinline__ void cp_commit() {
    asm volatile("cp.async.commit_group;" ::: "memory");
}
template<int N>
__device__ __forceinline__ void cp_wait() {
    asm volatile("cp.async.wait_group %0;" :: "n"(N) : "memory");
}
__device__ __forceinline__ int gather_off(int row) {
    int seq = row / TT, t = row % TT;
    int b = seq / VV, v = seq % VV;
    return ((b*TT + t)*VV + v) * DM;
}

// ---------------- weight prep: round 4 weight matrices to tf32 ----------------
__global__ void wprep_kernel(const float* __restrict__ qkvw,
                             const float* __restrict__ projw,
                             const float* __restrict__ w1,
                             const float* __restrict__ w2,
                             float* __restrict__ dst)
{
    int i = blockIdx.x * blockDim.x + threadIdx.x;
    if (i >= WTOTAL) return;
    float v;
    if      (i < WOFF_PROJ) v = qkvw[i];
    else if (i < WOFF_W1)   v = projw[i - WOFF_PROJ];
    else if (i < WOFF_W2)   v = w1[i - WOFF_W1];
    else                    v = w2[i - WOFF_W2];
    dst[i] = f2tff(v);
}

// ---------------- LayerNorm with gather (LN1); output tf32-rounded ------------
__global__ void ln_kernel(const float* __restrict__ in,
                          const float* __restrict__ gw,
                          const float* __restrict__ bw,
                          float* __restrict__ out)
{
    int m   = blockIdx.x;
    int tid = threadIdx.x;         // 128 threads
    int seq = m / TT, t = m % TT;
    int b = seq / VV, v = seq % VV;
    const float* src = in + ((b*TT + t)*VV + v) * DM;
    float x = src[tid];

    __shared__ float red1[4], red2[4];
    float s = x;
    #pragma unroll
    for (int o = 16; o > 0; o >>= 1) s += __shfl_down_sync(0xffffffffu, s, o);
    if ((tid & 31) == 0) red1[tid >> 5] = s;
    __syncthreads();
    float mean = (red1[0] + red1[1] + red1[2] + red1[3]) * (1.0f / DM);

    float dx = x - mean;
    float s2 = dx * dx;
    #pragma unroll
    for (int o = 16; o > 0; o >>= 1) s2 += __shfl_down_sync(0xffffffffu, s2, o);
    if ((tid & 31) == 0) red2[tid >> 5] = s2;
    __syncthreads();
    float var = (red2[0] + red2[1] + red2[2] + red2[3]) * (1.0f / DM);

    out[m * DM + tid] = f2tff(dx * rsqrtf(var + 1e-5f) * gw[tid] + bw[tid]);
}

// ---------------- tf32 tensor-core GEMM ---------------------------------------
// Inputs A,B must already be tf32-rounded. Epilogues:
// EPI 1: + bias + gather(x) -> xf (C) fp32; fused LayerNorm -> z (C2) tf32
// EPI 2: gelu_exact(+ bias) -> C  (tf32-rounded)
// EPI 3: + bias + extra[row] -> scatter to (B,T,V,D) output
// EPI 4: + bias -> scatter to head-major q/k/v parts
// AG  1: A is head-major attention output [H][NTOK][16]
template<int KDIM, int NDIM, int EPI, int AG>
__global__ void __launch_bounds__(256, 2)
mma_gemm(const float* __restrict__ A,
         const float* __restrict__ B,
         const float* __restrict__ bias,
         const float* __restrict__ extra,
         float* __restrict__ C,
         float* __restrict__ C2,
         const float* __restrict__ lng,
         const float* __restrict__ lnb)
{
    extern __shared__ float smem[];
    float* As = smem;          // [2][BM][AS_STRIDE]
    float* Bs = smem + BOFF;   // [2][BK][BS_STRIDE]
    uint32_t sbase = (uint32_t)__cvta_generic_to_shared(smem);

    const int tid  = threadIdx.x;
    const int bx   = blockIdx.x, by = blockIdx.y;
    const int lane = tid & 31, warp = tid >> 5;
    const int wm   = (warp & 1) * 64;     // 2 warps along M
    const int wn   = (warp >> 1) * 32;    // 4 warps along N
    const int g    = lane >> 2, tig = lane & 3;

    // global load mapping
    const int a_r = tid >> 3, a_k = (tid & 7) * 4;     // + c*32 rows
    const int b_r = tid >> 5, b_n = (tid & 31) * 4;    // + c*8 rows
    const float* Ag = A + (long)(by*BM + a_r) * KDIM + a_k;
    const float* Bg = B + (long)b_r * NDIM + bx*BN + b_n;

    const int NK = KDIM / BK;
    float acc[4][4][4] = {};

    auto load_tile = [&](int kt, int s) {
        #pragma unroll
        for (int c = 0; c < 4; c++) {
            int off = (s*BM + c*32 + a_r) * AS_STRIDE + a_k;
            if (AG) {
                int k = kt*BK + a_k;
                int row = by*BM + c*32 + a_r;
                cp16(sbase + 4*off, A + (long)((k >> 4)*NTOK + row)*HD + (k & 15));
            } else {
                cp16(sbase + 4*off, Ag + (long)c*32*KDIM + kt*BK);
            }
        }
        #pragma unroll
        for (int c = 0; c < 4; c++) {
            int off = BOFF + (s*BK + c*8 + b_r) * BS_STRIDE + b_n;
            cp16(sbase + 4*off, Bg + (long)(kt*BK + c*8) * NDIM);
        }
    };

    load_tile(0, 0);
    cp_commit();

    #pragma unroll 1
    for (int kt = 0; kt < NK; kt++) {
        if (kt + 1 < NK) {
            load_tile(kt + 1, (kt + 1) & 1);
            cp_commit();
            cp_wait<1>();
        } else {
            cp_wait<0>();
        }
        __syncthreads();

        const int s = kt & 1;
        #pragma unroll
        for (int ks = 0; ks < BK; ks += 8) {
            uint32_t af[4][4], bf[4][2];
            #pragma unroll
            for (int mi = 0; mi < 4; mi++) {
                int r0 = (s*BM + wm + mi*16 + g) * AS_STRIDE;
                af[mi][0] = __float_as_uint(As[r0               + ks + tig]);
                af[mi][1] = __float_as_uint(As[r0 + 8*AS_STRIDE + ks + tig]);
                af[mi][2] = __float_as_uint(As[r0               + ks + tig + 4]);
                af[mi][3] = __float_as_uint(As[r0 + 8*AS_STRIDE + ks + tig + 4]);
            }
            #pragma unroll
            for (int ni = 0; ni < 4; ni++) {
                int cc = wn + ni*8 + g;
                bf[ni][0] = __float_as_uint(Bs[(s*BK + ks + tig    ) * BS_STRIDE + cc]);
                bf[ni][1] = __float_as_uint(Bs[(s*BK + ks + tig + 4) * BS_STRIDE + cc]);
            }
            #pragma unroll
            for (int mi = 0; mi < 4; mi++)
                #pragma unroll
                for (int ni = 0; ni < 4; ni++)
                    mma8(acc[mi][ni], af[mi], bf[ni]);
        }
        __syncthreads();
    }

    // ---------------- epilogue ----------------
    if (EPI == 1) {
        // proj + residual -> xf (C), then fused LayerNorm -> z (C2)
        float* red = smem;   // [128 rows][4 wn-groups] float2 (sum, sumsq)
        const int wngrp = warp >> 1;

        float rsum[4][2], rsq[4][2];
        #pragma unroll
        for (int mi = 0; mi < 4; mi++) {
            #pragma unroll
            for (int rr = 0; rr < 2; rr++) {
                int rloc = wm + mi*16 + rr*8 + g;
                int row  = by*BM + rloc;
                int go   = gather_off(row);
                float ls = 0.f, lq = 0.f;
                #pragma unroll
                for (int ni = 0; ni < 4; ni++) {
                    int col = wn + ni*8 + 2*tig;
                    float vx = acc[mi][ni][rr*2+0] + bias[col] + extra[go + col];
                    float vy = acc[mi][ni][rr*2+1] + bias[col+1] + extra[go + col + 1];
                    acc[mi][ni][rr*2+0] = vx;
                    acc[mi][ni][rr*2+1] = vy;
                    float2 r = {vx, vy};
                    *(float2*)&C[(long)row*DM + col] = r;
                    ls += vx + vy;
                    lq += vx*vx + vy*vy;
                }
                rsum[mi][rr] = ls; rsq[mi][rr] = lq;
            }
        }
        // reduce across tig group (lanes 4g..4g+3)
        #pragma unroll
        for (int mi = 0; mi < 4; mi++)
            #pragma unroll
            for (int rr = 0; rr < 2; rr++) {
                #pragma unroll
                for (int o = 1; o <= 2; o <<= 1) {
                    rsum[mi][rr] += __shfl_xor_sync(0xffffffffu, rsum[mi][rr], o);
                    rsq[mi][rr]  += __shfl_xor_sync(0xffffffffu, rsq[mi][rr],  o);
                }
            }
        if (tig == 0) {
            #pragma unroll
            for (int mi = 0; mi < 4; mi++)
                #pragma unroll
                for (int rr = 0; rr < 2; rr++) {
                    int rloc = wm + mi*16 + rr*8 + g;
                    red[(rloc*4 + wngrp)*2 + 0] = rsum[mi][rr];
                    red[(rloc*4 + wngrp)*2 + 1] = rsq[mi][rr];
                }
        }
        __syncthreads();
        #pragma unroll
        for (int mi = 0; mi < 4; mi++) {
            #pragma unroll
            for (int rr = 0; rr < 2; rr++) {
                int rloc = wm + mi*16 + rr*8 + g;
                int row  = by*BM + rloc;
                float s = 0.f, q = 0.f;
                #pragma unroll
                for (int w = 0; w < 4; w++) {
                    s += red[(rloc*4 + w)*2 + 0];
                    q += red[(rloc*4 + w)*2 + 1];
                }
                float mean = s * (1.0f/DM);
                float var  = q * (1.0f/DM) - mean*mean;
                float inv  = rsqrtf(var + 1e-5f);
                #pragma unroll
                for (int ni = 0; ni < 4; ni++) {
                    int col = wn + ni*8 + 2*tig;
                    float zx = (acc[mi][ni][rr*2+0] - mean)*inv*lng[col]   + lnb[col];
                    float zy = (acc[mi][ni][rr*2+1] - mean)*inv*lng[col+1] + lnb[col+1];
                    float2 r = {f2tff(zx), f2tff(zy)};
                    *(float2*)&C2[(long)row*DM + col] = r;
                }
            }
        }
        return;
    }

    #pragma unroll
    for (int mi = 0; mi < 4; mi++) {
        #pragma unroll
        for (int rr = 0; rr < 2; rr++) {
            int row = by*BM + wm + mi*16 + rr*8 + g;
            int go = 0;
            if (EPI == 3) go = gather_off(row);
            #pragma unroll
            for (int ni = 0; ni < 4; ni++) {
                int col = bx*BN + wn + ni*8 + 2*tig;
                float vx = acc[mi][ni][rr*2 + 0] + bias[col];
                float vy = acc[mi][ni][rr*2 + 1] + bias[col + 1];
                if (EPI == 2) {
                    vx = 0.5f * vx * (1.0f + erff(vx * 0.70710678118654752f));
                    vy = 0.5f * vy * (1.0f + erff(vy * 0.70710678118654752f));
                    float2 r = {f2tff(vx), f2tff(vy)};
                    *(float2*)&C[(long)row*NDIM + col] = r;
                } else if (EPI == 3) {
                    vx += extra[(long)row*DM + col];
                    vy += extra[(long)row*DM + col + 1];
                    float2 r = {vx, vy};
                    *(float2*)&C[go + col] = r;
                } else {  // EPI 4: scatter to head-major q/k/v
                    int part = col >> 7, rem = col & 127;
                    int h = rem >> 4, d = rem & 15;
                    float2 r = {vx, vy};
                    *(float2*)&C[(long)part*PART + ((long)h*NTOK + row)*HD + d] = r;
                }
            }
        }
    }
}

// ---------------- Attention: one block per (seq, head), head-major IO ---------
__global__ void attn_kernel(const float* __restrict__ qkv,
                            const float* __restrict__ logit_scale,
                            const float* __restrict__ rpb,
                            float* __restrict__ out)
{
    const int seq = blockIdx.x;
    const int h   = blockIdx.y;
    const int t   = threadIdx.x;   // 256: one query row per thread

    __shared__ float Ks[TT][HD];
    __shared__ float Vs[TT][HD];
    __shared__ float bs[NBIAS + 1];

    for (int i = t; i < NBIAS; i += TT) bs[i] = rpb[h * NBIAS + i];

    const long idx = ((long)h*NTOK + seq*TT + t) * HD;
    const float* qb = qkv + idx;
    const float* kb = qkv + PART + idx;
    const float* vb = qkv + 2L*PART + idx;

    float q[HD], kv[HD];
    #pragma unroll
    for (int i = 0; i < HD; i += 4) {
        float4 f = *(const float4*)(qb + i);
        q[i] = f.x; q[i+1] = f.y; q[i+2] = f.z; q[i+3] = f.w;
    }
    #pragma unroll
    for (int i = 0; i < HD; i += 4) {
        float4 f = *(const float4*)(kb + i);
        kv[i] = f.x; kv[i+1] = f.y; kv[i+2] = f.z; kv[i+3] = f.w;
    }
    float kss = 0.f;
    #pragma unroll
    for (int i = 0; i < HD; i++) kss += kv[i] * kv[i];
    float kinv = 1.0f / fmaxf(sqrtf(kss), 1e-12f);
    #pragma unroll
    for (int i = 0; i < HD; i += 4) {
        float4 f; f.x = kv[i]*kinv; f.y = kv[i+1]*kinv; f.z = kv[i+2]*kinv; f.w = kv[i+3]*kinv;
        *(float4*)&Ks[t][i] = f;
    }
    #pragma unroll
    for (int i = 0; i < HD; i += 4) {
        *(float4*)&Vs[t][i] = *(const float4*)(vb + i);
    }

    float ls    = logit_scale[h];
    float scale = __expf(fminf(ls, 4.6051701859880914f));   // log(100)
    float qss = 0.f;
    #pragma unroll
    for (int i = 0; i < HD; i++) qss += q[i] * q[i];
    float qf = scale * 0.25f / fmaxf(sqrtf(qss), 1e-12f);
    #pragma unroll
    for (int i = 0; i < HD; i++) q[i] *= qf;

    __syncthreads();

    float mrun = -1e30f, l = 0.f, o[HD] = {};
    #pragma unroll 4
    for (int s = 0; s < TT; s++) {
        float dot = 0.f;
        #pragma unroll
        for (int i = 0; i < HD; i++) dot += q[i] * Ks[s][i];
        float sc = dot + bs[t - s + (MAXT - 1)];
        float mn = fmaxf(mrun, sc);
        float c  = __expf(mrun - mn);
        float p  = __expf(sc - mn);
        l = l * c + p;
        #pragma unroll
        for (int i = 0; i < HD; i++) o[i] = o[i] * c + p * Vs[s][i];
        mrun = mn;
    }
    float il = 1.0f / l;
    float* dst = out + idx;
    #pragma unroll
    for (int i = 0; i < HD; i += 4) {
        float4 f;
        f.x = f2tff(o[i]*il);   f.y = f2tff(o[i+1]*il);
        f.z = f2tff(o[i+2]*il); f.w = f2tff(o[i+3]*il);
        *(float4*)&dst[i] = f;
    }
}

// -------------------------------- launch --------------------------------------
extern "C" void kernel_launch(void* const* d_in, const int* in_sizes, int n_in,
                              void* d_out, int out_size)
{
    const float* x     = (const float*)d_in[0];
    const float* ln1g  = (const float*)d_in[1];
    const float* ln1b  = (const float*)d_in[2];
    const float* qkvw  = (const float*)d_in[3];
    const float* qkvb  = (const float*)d_in[4];
    const float* projw = (const float*)d_in[5];
    const float* projb = (const float*)d_in[6];
    const float* ls    = (const float*)d_in[7];
    const float* rpb   = (const float*)d_in[8];
    const float* ln2g  = (const float*)d_in[9];
    const float* ln2b  = (const float*)d_in[10];
    const float* w1    = (const float*)d_in[11];
    const float* b1    = (const float*)d_in[12];
    const float* w2    = (const float*)d_in[13];
    const float* b2    = (const float*)d_in[14];
    float* out = (float*)d_out;

    float *xn, *qkv, *attn, *xf, *z, *hb, *wbuf;
    cudaGetSymbolAddress((void**)&xn,   g_xn);
    cudaGetSymbolAddress((void**)&qkv,  g_qkv);
    cudaGetSymbolAddress((void**)&attn, g_attn);
    cudaGetSymbolAddress((void**)&xf,   g_xf);
    cudaGetSymbolAddress((void**)&z,    g_z);
    cudaGetSymbolAddress((void**)&hb,   g_h);
    cudaGetSymbolAddress((void**)&wbuf, g_w);

    cudaFuncSetAttribute(mma_gemm<128, 384, 4, 0>, cudaFuncAttributeMaxDynamicSharedMemorySize, GEMM_SMEM);
    cudaFuncSetAttribute(mma_gemm<128, 128, 1, 1>, cudaFuncAttributeMaxDynamicSharedMemorySize, GEMM_SMEM);
    cudaFuncSetAttribute(mma_gemm<128, 512, 2, 0>, cudaFuncAttributeMaxDynamicSharedMemorySize, GEMM_SMEM);
    cudaFuncSetAttribute(mma_gemm<512, 128, 3, 0>, cudaFuncAttributeMaxDynamicSharedMemorySize, GEMM_SMEM);

    // 0) round weights to tf32 once per launch
    wprep_kernel<<<(WTOTAL + 255)/256, 256>>>(qkvw, projw, w1, w2, wbuf);
    // 1) gather + LN1 (tf32 out)
    ln_kernel<<<NTOK, 128>>>(x, ln1g, ln1b, xn);
    // 2) QKV projection -> head-major q/k/v
    mma_gemm<128, 384, 4, 0><<<dim3(3, NTOK/BM), 256, GEMM_SMEM>>>(
        xn, wbuf + WOFF_QKV, qkvb, nullptr, qkv, nullptr, nullptr, nullptr);
    // 3) attention per (seq, head) -> head-major attn (tf32 out)
    attn_kernel<<<dim3(SEQS, HH), TT>>>(qkv, ls, rpb, attn);
    // 4) proj + residual -> xf, fused LN2 -> z
    mma_gemm<128, 128, 1, 1><<<dim3(1, NTOK/BM), 256, GEMM_SMEM>>>(
        attn, wbuf + WOFF_PROJ, projb, x, xf, z, ln2g, ln2b);
    // 5) FFN1 + exact GELU (tf32 out)
    mma_gemm<128, 512, 2, 0><<<dim3(4, NTOK/BM), 256, GEMM_SMEM>>>(
        z, wbuf + WOFF_W1, b1, nullptr, hb, nullptr, nullptr, nullptr);
    // 6) FFN2 + residual -> scatter to (B,T,V,D) output
    mma_gemm<512, 128, 3, 0><<<dim3(1, NTOK/BM), 256, GEMM_SMEM>>>(
        hb, wbuf + WOFF_W2, b2, xf, out, nullptr, nullptr, nullptr);
}

// round 4
// speedup vs baseline: 3.2117x; 1.6237x over previous
#include <cuda_runtime.h>
#include <math.h>
#include <stdint.h>

// Problem constants
#define BB   16
#define TT   256
#define VV   25
#define DM   128
#define HH   8
#define HD   16
#define MAXT 300
#define SEQS (BB*VV)          // 400
#define NTOK (SEQS*TT)        // 102400
#define NBIAS (2*MAXT-1)      // 599
#define PART (HH*NTOK*HD)     // per q/k/v head-major part size

// GEMM tiling
#define BM 128
#define BN 128
#define BK 32
#define AS_STRIDE (BK + 4)    // 36 floats  (bank = 4g+tig : conflict-free)
#define BS_STRIDE (BN + 8)    // 136 floats (bank = 8tig+g : conflict-free)
#define BOFF (2*BM*AS_STRIDE) // float offset of B tiles in smem
#define GEMM_SMEM ((2*BM*AS_STRIDE + 2*BK*BS_STRIDE)*4)   // 71680 bytes

// weight-prep segment offsets (tf32-rounded copies)
#define WOFF_QKV  0
#define WOFF_PROJ 49152
#define WOFF_W1   65536
#define WOFF_W2   131072
#define WTOTAL    196608

// attention smem layout (floats)
#define QSS 20                      // Q/K row stride
#define VSS 24                      // V row stride
#define AQ_OFF 0
#define AK_OFF (TT*QSS)             // 5120
#define AV_OFF (2*TT*QSS)           // 10240
#define AB_OFF (2*TT*QSS + TT*VSS)  // 16384
#define ATTN_SMEM ((AB_OFF + NBIAS + 1)*4)   // 67936 bytes

// ---------------- scratch (device globals; no runtime allocation) -------------
__device__ float g_xn  [NTOK*DM];     // LN1 output (tf32-rounded)
__device__ float g_qkv [NTOK*3*DM];   // q/k/v, head-major [3][H][NTOK][16]
__device__ float g_attn[NTOK*DM];     // attention output, head-major (tf32)
__device__ float g_xf  [NTOK*DM];     // after proj + residual (fp32)
__device__ float g_z   [NTOK*DM];     // LN2 output (tf32-rounded)
__device__ float g_h   [NTOK*4*DM];   // FFN hidden (tf32-rounded)
__device__ float g_w   [WTOTAL];      // tf32-rounded weights

// ---------------- small helpers -----------------------------------------------
__device__ __forceinline__ uint32_t f2tf(float v) {
    uint32_t r;
    asm("cvt.rna.tf32.f32 %0, %1;" : "=r"(r) : "f"(v));
    return r;
}
__device__ __forceinline__ float f2tff(float v) { return __uint_as_float(f2tf(v)); }

__device__ __forceinline__ void mma8(float* c, const uint32_t* a, const uint32_t* b) {
    asm volatile(
        "mma.sync.aligned.m16n8k8.row.col.f32.tf32.tf32.f32 "
        "{%0,%1,%2,%3}, {%4,%5,%6,%7}, {%8,%9}, {%0,%1,%2,%3};"
        : "+f"(c[0]), "+f"(c[1]), "+f"(c[2]), "+f"(c[3])
        : "r"(a[0]), "r"(a[1]), "r"(a[2]), "r"(a[3]), "r"(b[0]), "r"(b[1]));
}
__device__ __forceinline__ void cp16(uint32_t dst, const float* src) {
    asm volatile("cp.async.cg.shared.global [%0], [%1], 16;" :: "r"(dst), "l"(src));
}
__device__ __forceinline__ void cp_commit() {
    asm volatile("cp.async.commit_group;" ::: "memory");
}
template<int N>
__device__ __forceinline__ void cp_wait() {
    asm volatile("cp.async.wait_group %0;" :: "n"(N) : "memory");
}
__device__ __forceinline__ int gather_off(int row) {
    int seq = row / TT, t = row % TT;
    int b = seq / VV, v = seq % VV;
    return ((b*TT + t)*VV + v) * DM;
}

// ---------------- weight prep: round 4 weight matrices to tf32 ----------------
__global__ void wprep_kernel(const float* __restrict__ qkvw,
                             const float* __restrict__ projw,
                             const float* __restrict__ w1,
                             const float* __restrict__ w2,
                             float* __restrict__ dst)
{
    int i = blockIdx.x * blockDim.x + threadIdx.x;
    if (i >= WTOTAL) return;
    float v;
    if      (i < WOFF_PROJ) v = qkvw[i];
    else if (i < WOFF_W1)   v = projw[i - WOFF_PROJ];
    else if (i < WOFF_W2)   v = w1[i - WOFF_W1];
    else                    v = w2[i - WOFF_W2];
    dst[i] = f2tff(v);
}

// ---------------- LayerNorm with gather (LN1); output tf32-rounded ------------
__global__ void ln_kernel(const float* __restrict__ in,
                          const float* __restrict__ gw,
                          const float* __restrict__ bw,
                          float* __restrict__ out)
{
    int m   = blockIdx.x;
    int tid = threadIdx.x;         // 128 threads
    int seq = m / TT, t = m % TT;
    int b = seq / VV, v = seq % VV;
    const float* src = in + ((b*TT + t)*VV + v) * DM;
    float x = src[tid];

    __shared__ float red1[4], red2[4];
    float s = x;
    #pragma unroll
    for (int o = 16; o > 0; o >>= 1) s += __shfl_down_sync(0xffffffffu, s, o);
    if ((tid & 31) == 0) red1[tid >> 5] = s;
    __syncthreads();
    float mean = (red1[0] + red1[1] + red1[2] + red1[3]) * (1.0f / DM);

    float dx = x - mean;
    float s2 = dx * dx;
    #pragma unroll
    for (int o = 16; o > 0; o >>= 1) s2 += __shfl_down_sync(0xffffffffu, s2, o);
    if ((tid & 31) == 0) red2[tid >> 5] = s2;
    __syncthreads();
    float var = (red2[0] + red2[1] + red2[2] + red2[3]) * (1.0f / DM);

    out[m * DM + tid] = f2tff(dx * rsqrtf(var + 1e-5f) * gw[tid] + bw[tid]);
}

// ---------------- tf32 tensor-core GEMM ---------------------------------------
// EPI 1: + bias + gather(x) -> xf (C) fp32; fused LayerNorm -> z (C2) tf32
// EPI 2: gelu_exact(+ bias) -> C  (tf32-rounded)
// EPI 3: + bias + extra[row] -> scatter to (B,T,V,D) output
// EPI 4: + bias -> scatter to head-major q/k/v parts
// AG  1: A is head-major attention output [H][NTOK][16]
template<int KDIM, int NDIM, int EPI, int AG>
__global__ void __launch_bounds__(256, 2)
mma_gemm(const float* __restrict__ A,
         const float* __restrict__ B,
         const float* __restrict__ bias,
         const float* __restrict__ extra,
         float* __restrict__ C,
         float* __restrict__ C2,
         const float* __restrict__ lng,
         const float* __restrict__ lnb)
{
    extern __shared__ float smem[];
    float* As = smem;          // [2][BM][AS_STRIDE]
    float* Bs = smem + BOFF;   // [2][BK][BS_STRIDE]
    uint32_t sbase = (uint32_t)__cvta_generic_to_shared(smem);

    const int tid  = threadIdx.x;
    const int bx   = blockIdx.x, by = blockIdx.y;
    const int lane = tid & 31, warp = tid >> 5;
    const int wm   = (warp & 1) * 64;
    const int wn   = (warp >> 1) * 32;
    const int g    = lane >> 2, tig = lane & 3;

    const int a_r = tid >> 3, a_k = (tid & 7) * 4;
    const int b_r = tid >> 5, b_n = (tid & 31) * 4;
    const float* Ag = A + (long)(by*BM + a_r) * KDIM + a_k;
    const float* Bg = B + (long)b_r * NDIM + bx*BN + b_n;

    const int NK = KDIM / BK;
    float acc[4][4][4] = {};

    auto load_tile = [&](int kt, int s) {
        #pragma unroll
        for (int c = 0; c < 4; c++) {
            int off = (s*BM + c*32 + a_r) * AS_STRIDE + a_k;
            if (AG) {
                int k = kt*BK + a_k;
                int row = by*BM + c*32 + a_r;
                cp16(sbase + 4*off, A + (long)((k >> 4)*NTOK + row)*HD + (k & 15));
            } else {
                cp16(sbase + 4*off, Ag + (long)c*32*KDIM + kt*BK);
            }
        }
        #pragma unroll
        for (int c = 0; c < 4; c++) {
            int off = BOFF + (s*BK + c*8 + b_r) * BS_STRIDE + b_n;
            cp16(sbase + 4*off, Bg + (long)(kt*BK + c*8) * NDIM);
        }
    };

    load_tile(0, 0);
    cp_commit();

    #pragma unroll 1
    for (int kt = 0; kt < NK; kt++) {
        if (kt + 1 < NK) {
            load_tile(kt + 1, (kt + 1) & 1);
            cp_commit();
            cp_wait<1>();
        } else {
            cp_wait<0>();
        }
        __syncthreads();

        const int s = kt & 1;
        #pragma unroll
        for (int ks = 0; ks < BK; ks += 8) {
            uint32_t af[4][4], bf[4][2];
            #pragma unroll
            for (int mi = 0; mi < 4; mi++) {
                int r0 = (s*BM + wm + mi*16 + g) * AS_STRIDE;
                af[mi][0] = __float_as_uint(As[r0               + ks + tig]);
                af[mi][1] = __float_as_uint(As[r0 + 8*AS_STRIDE + ks + tig]);
                af[mi][2] = __float_as_uint(As[r0               + ks + tig + 4]);
                af[mi][3] = __float_as_uint(As[r0 + 8*AS_STRIDE + ks + tig + 4]);
            }
            #pragma unroll
            for (int ni = 0; ni < 4; ni++) {
                int cc = wn + ni*8 + g;
                bf[ni][0] = __float_as_uint(Bs[(s*BK + ks + tig    ) * BS_STRIDE + cc]);
                bf[ni][1] = __float_as_uint(Bs[(s*BK + ks + tig + 4) * BS_STRIDE + cc]);
            }
            #pragma unroll
            for (int mi = 0; mi < 4; mi++)
                #pragma unroll
                for (int ni = 0; ni < 4; ni++)
                    mma8(acc[mi][ni], af[mi], bf[ni]);
        }
        __syncthreads();
    }

    // ---------------- epilogue ----------------
    if (EPI == 1) {
        float* red = smem;
        const int wngrp = warp >> 1;

        float rsum[4][2], rsq[4][2];
        #pragma unroll
        for (int mi = 0; mi < 4; mi++) {
            #pragma unroll
            for (int rr = 0; rr < 2; rr++) {
                int rloc = wm + mi*16 + rr*8 + g;
                int row  = by*BM + rloc;
                int go   = gather_off(row);
                float ls = 0.f, lq = 0.f;
                #pragma unroll
                for (int ni = 0; ni < 4; ni++) {
                    int col = wn + ni*8 + 2*tig;
                    float vx = acc[mi][ni][rr*2+0] + bias[col] + extra[go + col];
                    float vy = acc[mi][ni][rr*2+1] + bias[col+1] + extra[go + col + 1];
                    acc[mi][ni][rr*2+0] = vx;
                    acc[mi][ni][rr*2+1] = vy;
                    float2 r = {vx, vy};
                    *(float2*)&C[(long)row*DM + col] = r;
                    ls += vx + vy;
                    lq += vx*vx + vy*vy;
                }
                rsum[mi][rr] = ls; rsq[mi][rr] = lq;
            }
        }
        #pragma unroll
        for (int mi = 0; mi < 4; mi++)
            #pragma unroll
            for (int rr = 0; rr < 2; rr++) {
                #pragma unroll
                for (int o = 1; o <= 2; o <<= 1) {
                    rsum[mi][rr] += __shfl_xor_sync(0xffffffffu, rsum[mi][rr], o);
                    rsq[mi][rr]  += __shfl_xor_sync(0xffffffffu, rsq[mi][rr],  o);
                }
            }
        if (tig == 0) {
            #pragma unroll
            for (int mi = 0; mi < 4; mi++)
                #pragma unroll
                for (int rr = 0; rr < 2; rr++) {
                    int rloc = wm + mi*16 + rr*8 + g;
                    red[(rloc*4 + wngrp)*2 + 0] = rsum[mi][rr];
                    red[(rloc*4 + wngrp)*2 + 1] = rsq[mi][rr];
                }
        }
        __syncthreads();
        #pragma unroll
        for (int mi = 0; mi < 4; mi++) {
            #pragma unroll
            for (int rr = 0; rr < 2; rr++) {
                int rloc = wm + mi*16 + rr*8 + g;
                int row  = by*BM + rloc;
                float s = 0.f, q = 0.f;
                #pragma unroll
                for (int w = 0; w < 4; w++) {
                    s += red[(rloc*4 + w)*2 + 0];
                    q += red[(rloc*4 + w)*2 + 1];
                }
                float mean = s * (1.0f/DM);
                float var  = q * (1.0f/DM) - mean*mean;
                float inv  = rsqrtf(var + 1e-5f);
                #pragma unroll
                for (int ni = 0; ni < 4; ni++) {
                    int col = wn + ni*8 + 2*tig;
                    float zx = (acc[mi][ni][rr*2+0] - mean)*inv*lng[col]   + lnb[col];
                    float zy = (acc[mi][ni][rr*2+1] - mean)*inv*lng[col+1] + lnb[col+1];
                    float2 r = {f2tff(zx), f2tff(zy)};
                    *(float2*)&C2[(long)row*DM + col] = r;
                }
            }
        }
        return;
    }

    #pragma unroll
    for (int mi = 0; mi < 4; mi++) {
        #pragma unroll
        for (int rr = 0; rr < 2; rr++) {
            int row = by*BM + wm + mi*16 + rr*8 + g;
            int go = 0;
            if (EPI == 3) go = gather_off(row);
            #pragma unroll
            for (int ni = 0; ni < 4; ni++) {
                int col = bx*BN + wn + ni*8 + 2*tig;
                float vx = acc[mi][ni][rr*2 + 0] + bias[col];
                float vy = acc[mi][ni][rr*2 + 1] + bias[col + 1];
                if (EPI == 2) {
                    vx = 0.5f * vx * (1.0f + erff(vx * 0.70710678118654752f));
                    vy = 0.5f * vy * (1.0f + erff(vy * 0.70710678118654752f));
                    float2 r = {f2tff(vx), f2tff(vy)};
                    *(float2*)&C[(long)row*NDIM + col] = r;
                } else if (EPI == 3) {
                    vx += extra[(long)row*DM + col];
                    vy += extra[(long)row*DM + col + 1];
                    float2 r = {vx, vy};
                    *(float2*)&C[go + col] = r;
                } else {  // EPI 4: scatter to head-major q/k/v
                    int part = col >> 7, rem = col & 127;
                    int h = rem >> 4, d = rem & 15;
                    float2 r = {vx, vy};
                    *(float2*)&C[(long)part*PART + ((long)h*NTOK + row)*HD + d] = r;
                }
            }
        }
    }
}

// ---------------- Attention via tensor cores, one block per (seq, head) -------
// scores bounded (|qn.kn|<=1, scale<=100, /4, tiny bias) -> exp without max.
__global__ void __launch_bounds__(256, 2)
attn_mma_kernel(const float* __restrict__ qkv,
                const float* __restrict__ logit_scale,
                const float* __restrict__ rpb,
                float* __restrict__ out)
{
    extern __shared__ float sm[];
    float* Qs = sm + AQ_OFF;   // [256][20] tf32, normalized+scaled q
    float* Ks = sm + AK_OFF;   // [256][20] tf32, normalized k
    float* Vs = sm + AV_OFF;   // [256][24] tf32
    float* bs = sm + AB_OFF;   // [599]

    const int seq = blockIdx.x, h = blockIdx.y;
    const int t    = threadIdx.x;
    const int lane = t & 31, w = t >> 5;
    const int g    = lane >> 2, tig = lane & 3;

    for (int i = t; i < NBIAS; i += 256) bs[i] = rpb[h*NBIAS + i];

    const long idx = ((long)h*NTOK + seq*TT + t) * HD;
    const float scale = __expf(fminf(logit_scale[h], 4.6051701859880914f));

    // ---- load & normalize one q/k/v row per thread ----
    {
        float q[HD], k[HD], v[HD];
        #pragma unroll
        for (int i = 0; i < HD; i += 4) {
            float4 f = *(const float4*)(qkv + idx + i);
            q[i]=f.x; q[i+1]=f.y; q[i+2]=f.z; q[i+3]=f.w;
        }
        #pragma unroll
        for (int i = 0; i < HD; i += 4) {
            float4 f = *(const float4*)(qkv + PART + idx + i);
            k[i]=f.x; k[i+1]=f.y; k[i+2]=f.z; k[i+3]=f.w;
        }
        #pragma unroll
        for (int i = 0; i < HD; i += 4) {
            float4 f = *(const float4*)(qkv + 2L*PART + idx + i);
            v[i]=f.x; v[i+1]=f.y; v[i+2]=f.z; v[i+3]=f.w;
        }
        float qs = 0.f, ks = 0.f;
        #pragma unroll
        for (int i = 0; i < HD; i++) { qs += q[i]*q[i]; ks += k[i]*k[i]; }
        float qf = scale * 0.25f / fmaxf(sqrtf(qs), 1e-12f);
        float kf = 1.0f / fmaxf(sqrtf(ks), 1e-12f);
        #pragma unroll
        for (int i = 0; i < HD; i += 4) {
            float4 fq = {f2tff(q[i]*qf), f2tff(q[i+1]*qf), f2tff(q[i+2]*qf), f2tff(q[i+3]*qf)};
            float4 fk = {f2tff(k[i]*kf), f2tff(k[i+1]*kf), f2tff(k[i+2]*kf), f2tff(k[i+3]*kf)};
            float4 fv = {f2tff(v[i]),    f2tff(v[i+1]),    f2tff(v[i+2]),    f2tff(v[i+3])};
            *(float4*)&Qs[t*QSS + i] = fq;
            *(float4*)&Ks[t*QSS + i] = fk;
            *(float4*)&Vs[t*VSS + i] = fv;
        }
    }
    __syncthreads();

    // ---- per-warp: 32 query rows, s in chunks of 32 ----
    const int m0 = w * 32;

    uint32_t qa[2][2][4];
    #pragma unroll
    for (int mi = 0; mi < 2; mi++)
        #pragma unroll
        for (int ks = 0; ks < 2; ks++) {
            int r = m0 + mi*16 + g;
            qa[mi][ks][0] = __float_as_uint(Qs[r*QSS     + ks*8 + tig]);
            qa[mi][ks][1] = __float_as_uint(Qs[(r+8)*QSS + ks*8 + tig]);
            qa[mi][ks][2] = __float_as_uint(Qs[r*QSS     + ks*8 + tig + 4]);
            qa[mi][ks][3] = __float_as_uint(Qs[(r+8)*QSS + ks*8 + tig + 4]);
        }

    float oacc[2][2][4] = {};
    float lsum[2][2] = {};
    const int src1 = (lane & ~3) | (tig >> 1);
    const int src2 = src1 + 2;
    const bool odd = tig & 1;

    #pragma unroll 1
    for (int cc = 0; cc < 8; cc++) {
        const int s0 = cc * 32;
        float sacc[2][4][4] = {};

        #pragma unroll
        for (int ni = 0; ni < 4; ni++) {
            uint32_t kb[2][2];
            #pragma unroll
            for (int ks = 0; ks < 2; ks++) {
                int sr = s0 + ni*8 + g;
                kb[ks][0] = __float_as_uint(Ks[sr*QSS + ks*8 + tig]);
                kb[ks][1] = __float_as_uint(Ks[sr*QSS + ks*8 + tig + 4]);
            }
            #pragma unroll
            for (int mi = 0; mi < 2; mi++) {
                mma8(sacc[mi][ni], qa[mi][0], kb[0]);
                mma8(sacc[mi][ni], qa[mi][1], kb[1]);
            }
        }

        // bias + exp (no max needed: scores bounded) + row-sum
        #pragma unroll
        for (int mi = 0; mi < 2; mi++)
            #pragma unroll
            for (int ni = 0; ni < 4; ni++) {
                int scol = s0 + ni*8 + 2*tig;
                int r0   = m0 + mi*16 + g;
                float p0 = __expf(sacc[mi][ni][0] + bs[r0     - scol     + (MAXT-1)]);
                float p1 = __expf(sacc[mi][ni][1] + bs[r0     - scol - 1 + (MAXT-1)]);
                float p2 = __expf(sacc[mi][ni][2] + bs[r0 + 8 - scol     + (MAXT-1)]);
                float p3 = __expf(sacc[mi][ni][3] + bs[r0 + 8 - scol - 1 + (MAXT-1)]);
                sacc[mi][ni][0] = p0; sacc[mi][ni][1] = p1;
                sacc[mi][ni][2] = p2; sacc[mi][ni][3] = p3;
                lsum[mi][0] += p0 + p1;
                lsum[mi][1] += p2 + p3;
            }

        // O += P @ V : register-permute P fragments, MMA against V
        #pragma unroll
        for (int kk = 0; kk < 4; kk++) {
            uint32_t vb[2][2];
            #pragma unroll
            for (int ni = 0; ni < 2; ni++) {
                int vr = s0 + kk*8;
                vb[ni][0] = __float_as_uint(Vs[(vr + tig    )*VSS + ni*8 + g]);
                vb[ni][1] = __float_as_uint(Vs[(vr + tig + 4)*VSS + ni*8 + g]);
            }
            #pragma unroll
            for (int mi = 0; mi < 2; mi++) {
                float l0 = __shfl_sync(0xffffffffu, sacc[mi][kk][0], src1);
                float l1 = __shfl_sync(0xffffffffu, sacc[mi][kk][1], src1);
                float h0 = __shfl_sync(0xffffffffu, sacc[mi][kk][2], src1);
                float h1 = __shfl_sync(0xffffffffu, sacc[mi][kk][3], src1);
                float m2 = __shfl_sync(0xffffffffu, sacc[mi][kk][0], src2);
                float m3 = __shfl_sync(0xffffffffu, sacc[mi][kk][1], src2);
                float n2 = __shfl_sync(0xffffffffu, sacc[mi][kk][2], src2);
                float n3 = __shfl_sync(0xffffffffu, sacc[mi][kk][3], src2);
                uint32_t pa[4];
                pa[0] = f2tf(odd ? l1 : l0);
                pa[1] = f2tf(odd ? h1 : h0);
                pa[2] = f2tf(odd ? m3 : m2);
                pa[3] = f2tf(odd ? n3 : n2);
                mma8(oacc[mi][0], pa, vb[0]);
                mma8(oacc[mi][1], pa, vb[1]);
            }
        }
    }

    // ---- finalize: reduce l over the 4 lanes sharing each row, write out ----
    #pragma unroll
    for (int mi = 0; mi < 2; mi++)
        #pragma unroll
        for (int rr = 0; rr < 2; rr++) {
            float v = lsum[mi][rr];
            v += __shfl_xor_sync(0xffffffffu, v, 1);
            v += __shfl_xor_sync(0xffffffffu, v, 2);
            lsum[mi][rr] = 1.0f / v;
        }

    #pragma unroll
    for (int mi = 0; mi < 2; mi++) {
        int r0 = m0 + mi*16 + g;
        #pragma unroll
        for (int rr = 0; rr < 2; rr++) {
            long oidx = ((long)h*NTOK + seq*TT + r0 + rr*8) * HD;
            float il = lsum[mi][rr];
            #pragma unroll
            for (int ni = 0; ni < 2; ni++) {
                float2 r;
                r.x = f2tff(oacc[mi][ni][rr*2+0] * il);
                r.y = f2tff(oacc[mi][ni][rr*2+1] * il);
                *(float2*)&out[oidx + ni*8 + 2*tig] = r;
            }
        }
    }
}

// -------------------------------- launch --------------------------------------
extern "C" void kernel_launch(void* const* d_in, const int* in_sizes, int n_in,
                              void* d_out, int out_size)
{
    const float* x     = (const float*)d_in[0];
    const float* ln1g  = (const float*)d_in[1];
    const float* ln1b  = (const float*)d_in[2];
    const float* qkvw  = (const float*)d_in[3];
    const float* qkvb  = (const float*)d_in[4];
    const float* projw = (const float*)d_in[5];
    const float* projb = (const float*)d_in[6];
    const float* ls    = (const float*)d_in[7];
    const float* rpb   = (const float*)d_in[8];
    const float* ln2g  = (const float*)d_in[9];
    const float* ln2b  = (const float*)d_in[10];
    const float* w1    = (const float*)d_in[11];
    const float* b1    = (const float*)d_in[12];
    const float* w2    = (const float*)d_in[13];
    const float* b2    = (const float*)d_in[14];
    float* out = (float*)d_out;

    float *xn, *qkv, *attn, *xf, *z, *hb, *wbuf;
    cudaGetSymbolAddress((void**)&xn,   g_xn);
    cudaGetSymbolAddress((void**)&qkv,  g_qkv);
    cudaGetSymbolAddress((void**)&attn, g_attn);
    cudaGetSymbolAddress((void**)&xf,   g_xf);
    cudaGetSymbolAddress((void**)&z,    g_z);
    cudaGetSymbolAddress((void**)&hb,   g_h);
    cudaGetSymbolAddress((void**)&wbuf, g_w);

    cudaFuncSetAttribute(mma_gemm<128, 384, 4, 0>, cudaFuncAttributeMaxDynamicSharedMemorySize, GEMM_SMEM);
    cudaFuncSetAttribute(mma_gemm<128, 128, 1, 1>, cudaFuncAttributeMaxDynamicSharedMemorySize, GEMM_SMEM);
    cudaFuncSetAttribute(mma_gemm<128, 512, 2, 0>, cudaFuncAttributeMaxDynamicSharedMemorySize, GEMM_SMEM);
    cudaFuncSetAttribute(mma_gemm<512, 128, 3, 0>, cudaFuncAttributeMaxDynamicSharedMemorySize, GEMM_SMEM);
    cudaFuncSetAttribute(attn_mma_kernel, cudaFuncAttributeMaxDynamicSharedMemorySize, ATTN_SMEM);

    // 0) round weights to tf32 once per launch
    wprep_kernel<<<(WTOTAL + 255)/256, 256>>>(qkvw, projw, w1, w2, wbuf);
    // 1) gather + LN1 (tf32 out)
    ln_kernel<<<NTOK, 128>>>(x, ln1g, ln1b, xn);
    // 2) QKV projection -> head-major q/k/v
    mma_gemm<128, 384, 4, 0><<<dim3(3, NTOK/BM), 256, GEMM_SMEM>>>(
        xn, wbuf + WOFF_QKV, qkvb, nullptr, qkv, nullptr, nullptr, nullptr);
    // 3) tensor-core attention per (seq, head) -> head-major attn (tf32 out)
    attn_mma_kernel<<<dim3(SEQS, HH), 256, ATTN_SMEM>>>(qkv, ls, rpb, attn);
    // 4) proj + residual -> xf, fused LN2 -> z
    mma_gemm<128, 128, 1, 1><<<dim3(1, NTOK/BM), 256, GEMM_SMEM>>>(
        attn, wbuf + WOFF_PROJ, projb, x, xf, z, ln2g, ln2b);
    // 5) FFN1 + exact GELU (tf32 out)
    mma_gemm<128, 512, 2, 0><<<dim3(4, NTOK/BM), 256, GEMM_SMEM>>>(
        z, wbuf + WOFF_W1, b1, nullptr, hb, nullptr, nullptr, nullptr);
    // 6) FFN2 + residual -> scatter to (B,T,V,D) output
    mma_gemm<512, 128, 3, 0><<<dim3(1, NTOK/BM), 256, GEMM_SMEM>>>(
        hb, wbuf + WOFF_W2, b2, xf, out, nullptr, nullptr, nullptr);
}

// round 5
// speedup vs baseline: 5.1839x; 1.6141x over previous
#include <cuda_runtime.h>
#include <cuda_bf16.h>
#include <math.h>
#include <stdint.h>

// Problem constants
#define BB   16
#define TT   256
#define VV   25
#define DM   128
#define HH   8
#define HD   16
#define MAXT 300
#define SEQS (BB*VV)          // 400
#define NTOK (SEQS*TT)        // 102400
#define NBIAS (2*MAXT-1)      // 599
#define PART (HH*NTOK*HD)     // per q/k/v head-major part size (elements)

// GEMM tiling (bf16)
#define BM 128
#define BN 128
#define BK 32
#define NSTG 4
#define ASTR 40               // A row stride in halves (80B: ldmatrix conflict-free)
#define BSTR (BN + 8)         // 136 halves (272B: conflict-free)
#define SA (BM*ASTR)          // 5120 halves per A stage
#define SB (BK*BSTR)          // 4352 halves per B stage
#define STG (SA + SB)         // 9472 halves per stage
#define GEMM_SMEM (NSTG*STG*2)  // 75776 bytes

// weight-prep segment offsets (bf16 copies)
#define WOFF_QKV  0
#define WOFF_PROJ 49152
#define WOFF_W1   65536
#define WOFF_W2   131072
#define WTOTAL    196608

typedef __nv_bfloat16 bf16;

// ---------------- scratch (device globals; no runtime allocation) -------------
__device__ bf16  g_xn  [NTOK*DM];     // LN1 output
__device__ bf16  g_qkv [NTOK*3*DM];   // q/k/v, head-major [3][H][NTOK][16]
__device__ bf16  g_attn[NTOK*DM];     // attention output, head-major
__device__ float g_xf  [NTOK*DM];     // after proj + residual (fp32!)
__device__ bf16  g_z   [NTOK*DM];     // LN2 output
__device__ bf16  g_h   [NTOK*4*DM];   // FFN hidden
__device__ bf16  g_w   [WTOTAL];      // bf16 weights

// ---------------- helpers ------------------------------------------------------
__device__ __forceinline__ uint32_t packbf(float lo, float hi) {
    uint32_t r;
    asm("cvt.rn.bf16x2.f32 %0, %1, %2;" : "=r"(r) : "f"(hi), "f"(lo));
    return r;
}
__device__ __forceinline__ float2 unpk(uint32_t u) {
    __nv_bfloat162 h = *reinterpret_cast<__nv_bfloat162*>(&u);
    return make_float2(__bfloat162float(h.x), __bfloat162float(h.y));
}
__device__ __forceinline__ void mma16(float* c, const uint32_t* a, const uint32_t* b) {
    asm volatile(
        "mma.sync.aligned.m16n8k16.row.col.f32.bf16.bf16.f32 "
        "{%0,%1,%2,%3}, {%4,%5,%6,%7}, {%8,%9}, {%0,%1,%2,%3};"
        : "+f"(c[0]), "+f"(c[1]), "+f"(c[2]), "+f"(c[3])
        : "r"(a[0]), "r"(a[1]), "r"(a[2]), "r"(a[3]), "r"(b[0]), "r"(b[1]));
}
__device__ __forceinline__ void ldm_x4(uint32_t* r, uint32_t addr) {
    asm volatile("ldmatrix.sync.aligned.m8n8.x4.shared.b16 {%0,%1,%2,%3}, [%4];"
        : "=r"(r[0]), "=r"(r[1]), "=r"(r[2]), "=r"(r[3]) : "r"(addr));
}
__device__ __forceinline__ void ldm_x2(uint32_t* r, uint32_t addr) {
    asm volatile("ldmatrix.sync.aligned.m8n8.x2.shared.b16 {%0,%1}, [%2];"
        : "=r"(r[0]), "=r"(r[1]) : "r"(addr));
}
__device__ __forceinline__ void ldm_x2_t(uint32_t* r, uint32_t addr) {
    asm volatile("ldmatrix.sync.aligned.m8n8.x2.trans.shared.b16 {%0,%1}, [%2];"
        : "=r"(r[0]), "=r"(r[1]) : "r"(addr));
}
__device__ __forceinline__ void cp16(uint32_t dst, const void* src) {
    asm volatile("cp.async.cg.shared.global [%0], [%1], 16;" :: "r"(dst), "l"(src));
}
__device__ __forceinline__ void cp_commit() {
    asm volatile("cp.async.commit_group;" ::: "memory");
}
template<int N>
__device__ __forceinline__ void cp_wait() {
    asm volatile("cp.async.wait_group %0;" :: "n"(N) : "memory");
}
__device__ __forceinline__ int gather_off(int row) {
    int seq = row / TT, t = row % TT;
    int b = seq / VV, v = seq % VV;
    return ((b*TT + t)*VV + v) * DM;
}

// ---------------- weight prep: fp32 -> bf16 -------------------------------------
__global__ void wprep_kernel(const float* __restrict__ qkvw,
                             const float* __restrict__ projw,
                             const float* __restrict__ w1,
                             const float* __restrict__ w2,
                             bf16* __restrict__ dst)
{
    int i = blockIdx.x * blockDim.x + threadIdx.x;
    if (i >= WTOTAL) return;
    float v;
    if      (i < WOFF_PROJ) v = qkvw[i];
    else if (i < WOFF_W1)   v = projw[i - WOFF_PROJ];
    else if (i < WOFF_W2)   v = w1[i - WOFF_W1];
    else                    v = w2[i - WOFF_W2];
    dst[i] = __float2bfloat16(v);
}

// ---------------- LN1: warp per row, gather, bf16 out ---------------------------
__global__ void ln1_kernel(const float* __restrict__ in,
                           const float* __restrict__ gw,
                           const float* __restrict__ bw,
                           bf16* __restrict__ out)
{
    int m    = (blockIdx.x * blockDim.x + threadIdx.x) >> 5;
    int lane = threadIdx.x & 31;
    int seq = m / TT, t = m % TT;
    int b = seq / VV, v = seq % VV;
    const float* src = in + ((b*TT + t)*VV + v) * DM;

    float4 x = *(const float4*)(src + lane*4);
    float s = x.x + x.y + x.z + x.w;
    #pragma unroll
    for (int o = 16; o > 0; o >>= 1) s += __shfl_xor_sync(0xffffffffu, s, o);
    float mean = s * (1.0f / DM);

    float dx0 = x.x - mean, dx1 = x.y - mean, dx2 = x.z - mean, dx3 = x.w - mean;
    float q = dx0*dx0 + dx1*dx1 + dx2*dx2 + dx3*dx3;
    #pragma unroll
    for (int o = 16; o > 0; o >>= 1) q += __shfl_xor_sync(0xffffffffu, q, o);
    float inv = rsqrtf(q * (1.0f / DM) + 1e-5f);

    float4 gv = *(const float4*)(gw + lane*4);
    float4 bv = *(const float4*)(bw + lane*4);
    uint2 r;
    r.x = packbf(dx0*inv*gv.x + bv.x, dx1*inv*gv.y + bv.y);
    r.y = packbf(dx2*inv*gv.z + bv.z, dx3*inv*gv.w + bv.w);
    *(uint2*)(out + (long)m*DM + lane*4) = r;
}

// ---------------- bf16 tensor-core GEMM -----------------------------------------
// EPI 1: + bias + gather(x) -> xf (Cf fp32); fused LayerNorm -> z (Cb bf16)
// EPI 2: gelu_exact(+ bias) -> Cb bf16            (FFN1)
// EPI 3: + bias + extra[row] -> scatter fp32 out  (FFN2)
// EPI 4: + bias -> scatter head-major q/k/v (Cb)  (QKV)
// AG 1: A is head-major [H][NTOK][16] bf16
template<int KDIM, int NDIM, int EPI, int AG>
__global__ void __launch_bounds__(256, 2)
mma_gemm(const bf16* __restrict__ A,
         const bf16* __restrict__ B,
         const float* __restrict__ bias,
         const float* __restrict__ extra,
         float* __restrict__ Cf,
         bf16* __restrict__ Cb,
         const float* __restrict__ lng,
         const float* __restrict__ lnb)
{
    extern __shared__ bf16 smem[];
    uint32_t sbase = (uint32_t)__cvta_generic_to_shared(smem);

    const int tid  = threadIdx.x;
    const int bx   = blockIdx.x, by = blockIdx.y;
    const int lane = tid & 31, warp = tid >> 5;
    const int wm   = (warp & 1) * 64;
    const int wn   = (warp >> 1) * 32;
    const int g    = lane >> 2, tig = lane & 3;

    const int NK = KDIM / BK;
    float acc[4][4][4] = {};

    auto load_tile = [&](int kt, int slot) {
        uint32_t sb = sbase + 2*(slot*STG);
        // A tile: 512 cp16 / 256 threads = 2
        #pragma unroll
        for (int i = 0; i < 2; i++) {
            int id = tid + i*256;
            int r = id >> 2, c8 = (id & 3) * 8;
            uint32_t dst = sb + 2*(r*ASTR + c8);
            int row = by*BM + r;
            if (AG) {
                int k = kt*BK + c8;
                cp16(dst, A + ((long)((k >> 4)*NTOK + row))*HD + (k & 15));
            } else {
                cp16(dst, A + (long)row*KDIM + kt*BK + c8);
            }
        }
        // B tile: 512 cp16 / 256 = 2
        #pragma unroll
        for (int j = 0; j < 2; j++) {
            int id = tid + j*256;
            int r = id >> 4, c8 = (id & 15) * 8;
            uint32_t dst = sb + 2*(SA + r*BSTR + c8);
            cp16(dst, B + (long)(kt*BK + r)*NDIM + bx*BN + c8);
        }
    };

    #pragma unroll
    for (int s = 0; s < NSTG-1; s++) {
        if (s < NK) load_tile(s, s);
        cp_commit();
    }

    // fragment address offsets (halves)
    const int a_roff = (lane & 7) + ((lane >> 3) & 1) * 8;
    const int a_coff = (lane >> 4) * 8;
    const int b_roff = lane & 15;

    #pragma unroll 1
    for (int kt = 0; kt < NK; kt++) {
        cp_wait<NSTG-2>();
        __syncthreads();
        int lt = kt + NSTG - 1;
        if (lt < NK) load_tile(lt, lt & (NSTG-1));
        cp_commit();

        uint32_t abase = sbase + 2*((kt & (NSTG-1))*STG);
        uint32_t bbase = abase + 2*SA;

        #pragma unroll
        for (int ks = 0; ks < 2; ks++) {
            uint32_t af[4][4], bf[4][2];
            #pragma unroll
            for (int mi = 0; mi < 4; mi++)
                ldm_x4(af[mi], abase + 2*((wm + mi*16 + a_roff)*ASTR + ks*16 + a_coff));
            #pragma unroll
            for (int ni = 0; ni < 4; ni++)
                ldm_x2_t(bf[ni], bbase + 2*((ks*16 + b_roff)*BSTR + wn + ni*8));
            #pragma unroll
            for (int mi = 0; mi < 4; mi++)
                #pragma unroll
                for (int ni = 0; ni < 4; ni++)
                    mma16(acc[mi][ni], af[mi], bf[ni]);
        }
    }

    // ---------------- epilogue ----------------
    if (EPI == 1) {
        __syncthreads();                 // smem reuse for row reductions
        float* red = (float*)smem;       // [128 rows][4 groups][2]
        const int wngrp = warp >> 1;

        float rsum[4][2], rsq[4][2];
        #pragma unroll
        for (int mi = 0; mi < 4; mi++) {
            #pragma unroll
            for (int rr = 0; rr < 2; rr++) {
                int rloc = wm + mi*16 + rr*8 + g;
                int row  = by*BM + rloc;
                int go   = gather_off(row);
                float ls = 0.f, lq = 0.f;
                #pragma unroll
                for (int ni = 0; ni < 4; ni++) {
                    int col = wn + ni*8 + 2*tig;
                    float vx = acc[mi][ni][rr*2+0] + bias[col]   + extra[go + col];
                    float vy = acc[mi][ni][rr*2+1] + bias[col+1] + extra[go + col + 1];
                    acc[mi][ni][rr*2+0] = vx;
                    acc[mi][ni][rr*2+1] = vy;
                    float2 r = {vx, vy};
                    *(float2*)&Cf[(long)row*DM + col] = r;
                    ls += vx + vy;
                    lq += vx*vx + vy*vy;
                }
                rsum[mi][rr] = ls; rsq[mi][rr] = lq;
            }
        }
        #pragma unroll
        for (int mi = 0; mi < 4; mi++)
            #pragma unroll
            for (int rr = 0; rr < 2; rr++) {
                #pragma unroll
                for (int o = 1; o <= 2; o <<= 1) {
                    rsum[mi][rr] += __shfl_xor_sync(0xffffffffu, rsum[mi][rr], o);
                    rsq[mi][rr]  += __shfl_xor_sync(0xffffffffu, rsq[mi][rr],  o);
                }
            }
        if (tig == 0) {
            #pragma unroll
            for (int mi = 0; mi < 4; mi++)
                #pragma unroll
                for (int rr = 0; rr < 2; rr++) {
                    int rloc = wm + mi*16 + rr*8 + g;
                    red[(rloc*4 + wngrp)*2 + 0] = rsum[mi][rr];
                    red[(rloc*4 + wngrp)*2 + 1] = rsq[mi][rr];
                }
        }
        __syncthreads();
        #pragma unroll
        for (int mi = 0; mi < 4; mi++) {
            #pragma unroll
            for (int rr = 0; rr < 2; rr++) {
                int rloc = wm + mi*16 + rr*8 + g;
                int row  = by*BM + rloc;
                float s = 0.f, q = 0.f;
                #pragma unroll
                for (int w2 = 0; w2 < 4; w2++) {
                    s += red[(rloc*4 + w2)*2 + 0];
                    q += red[(rloc*4 + w2)*2 + 1];
                }
                float mean = s * (1.0f/DM);
                float var  = q * (1.0f/DM) - mean*mean;
                float inv  = rsqrtf(var + 1e-5f);
                #pragma unroll
                for (int ni = 0; ni < 4; ni++) {
                    int col = wn + ni*8 + 2*tig;
                    float zx = (acc[mi][ni][rr*2+0] - mean)*inv*lng[col]   + lnb[col];
                    float zy = (acc[mi][ni][rr*2+1] - mean)*inv*lng[col+1] + lnb[col+1];
                    *(uint32_t*)&Cb[(long)row*DM + col] = packbf(zx, zy);
                }
            }
        }
        return;
    }

    #pragma unroll
    for (int mi = 0; mi < 4; mi++) {
        #pragma unroll
        for (int rr = 0; rr < 2; rr++) {
            int row = by*BM + wm + mi*16 + rr*8 + g;
            int go = 0;
            if (EPI == 3) go = gather_off(row);
            #pragma unroll
            for (int ni = 0; ni < 4; ni++) {
                int col = bx*BN + wn + ni*8 + 2*tig;
                float vx = acc[mi][ni][rr*2 + 0] + bias[col];
                float vy = acc[mi][ni][rr*2 + 1] + bias[col + 1];
                if (EPI == 2) {
                    vx = 0.5f * vx * (1.0f + erff(vx * 0.70710678118654752f));
                    vy = 0.5f * vy * (1.0f + erff(vy * 0.70710678118654752f));
                    *(uint32_t*)&Cb[(long)row*NDIM + col] = packbf(vx, vy);
                } else if (EPI == 3) {
                    vx += extra[(long)row*DM + col];
                    vy += extra[(long)row*DM + col + 1];
                    float2 r = {vx, vy};
                    *(float2*)&Cf[go + col] = r;
                } else {  // EPI 4: head-major q/k/v
                    int part = col >> 7, rem = col & 127;
                    int hh = rem >> 4, d = rem & 15;
                    *(uint32_t*)&Cb[(long)part*PART + ((long)hh*NTOK + row)*HD + d] =
                        packbf(vx, vy);
                }
            }
        }
    }
}

// ---------------- bf16 tensor-core attention ------------------------------------
// One block per (seq, head); 8 warps x 32 query rows; s chunks of 32.
// Scores bounded (scale<=100 clamp, |qn.kn|<=1, /4) -> exp without max tracking.
// P accumulator packs DIRECTLY into bf16 A-fragments (no shuffles).
__global__ void __launch_bounds__(256)
attn_bf16_kernel(const bf16* __restrict__ qkv,
                 const float* __restrict__ logit_scale,
                 const float* __restrict__ rpb,
                 bf16* __restrict__ out)
{
    __shared__ __align__(16) bf16 Qs[TT*24];
    __shared__ __align__(16) bf16 Ks[TT*24];
    __shared__ __align__(16) bf16 Vs[TT*24];
    __shared__ float bs[NBIAS + 1];

    const int seq = blockIdx.x, h = blockIdx.y;
    const int t    = threadIdx.x;
    const int lane = t & 31, w = t >> 5;
    const int g    = lane >> 2, tig = lane & 3;

    for (int i = t; i < NBIAS; i += 256) bs[i] = rpb[h*NBIAS + i];

    const long idx = ((long)h*NTOK + seq*TT + t) * HD;
    const float scale = __expf(fminf(logit_scale[h], 4.6051701859880914f));

    {   // load one q/k/v row per thread, normalize q,k in fp32, store bf16
        uint4 qu0 = *(const uint4*)(qkv + idx);
        uint4 qu1 = *(const uint4*)(qkv + idx + 8);
        uint4 ku0 = *(const uint4*)(qkv + PART + idx);
        uint4 ku1 = *(const uint4*)(qkv + PART + idx + 8);
        uint4 vu0 = *(const uint4*)(qkv + 2L*PART + idx);
        uint4 vu1 = *(const uint4*)(qkv + 2L*PART + idx + 8);

        uint32_t uq[8] = {qu0.x,qu0.y,qu0.z,qu0.w, qu1.x,qu1.y,qu1.z,qu1.w};
        uint32_t uk[8] = {ku0.x,ku0.y,ku0.z,ku0.w, ku1.x,ku1.y,ku1.z,ku1.w};
        float q[16], k[16];
        float qs = 0.f, ks = 0.f;
        #pragma unroll
        for (int j = 0; j < 8; j++) {
            float2 fq = unpk(uq[j]), fk = unpk(uk[j]);
            q[2*j] = fq.x; q[2*j+1] = fq.y;
            k[2*j] = fk.x; k[2*j+1] = fk.y;
            qs += fq.x*fq.x + fq.y*fq.y;
            ks += fk.x*fk.x + fk.y*fk.y;
        }
        float qf = scale * 0.25f / fmaxf(sqrtf(qs), 1e-12f);
        float kf = 1.0f / fmaxf(sqrtf(ks), 1e-12f);
        uint32_t wq[8], wk[8];
        #pragma unroll
        for (int j = 0; j < 8; j++) {
            wq[j] = packbf(q[2*j]*qf, q[2*j+1]*qf);
            wk[j] = packbf(k[2*j]*kf, k[2*j+1]*kf);
        }
        *(uint4*)&Qs[t*24]     = make_uint4(wq[0],wq[1],wq[2],wq[3]);
        *(uint4*)&Qs[t*24 + 8] = make_uint4(wq[4],wq[5],wq[6],wq[7]);
        *(uint4*)&Ks[t*24]     = make_uint4(wk[0],wk[1],wk[2],wk[3]);
        *(uint4*)&Ks[t*24 + 8] = make_uint4(wk[4],wk[5],wk[6],wk[7]);
        *(uint4*)&Vs[t*24]     = vu0;
        *(uint4*)&Vs[t*24 + 8] = vu1;
    }
    __syncthreads();

    uint32_t sQ = (uint32_t)__cvta_generic_to_shared(Qs);
    uint32_t sK = (uint32_t)__cvta_generic_to_shared(Ks);
    uint32_t sV = (uint32_t)__cvta_generic_to_shared(Vs);

    const int m0 = w * 32;
    const int fr = (lane & 7) + ((lane >> 3) & 1) * 8;   // ldm x4 row offset
    const int fc = (lane >> 4) * 8;                      // ldm x4 col offset

    uint32_t qa[2][4];
    #pragma unroll
    for (int mi = 0; mi < 2; mi++)
        ldm_x4(qa[mi], sQ + 2*((m0 + mi*16 + fr)*24 + fc));

    float oacc[2][2][4] = {};
    float lsum[2][2] = {};

    #pragma unroll 1
    for (int cc = 0; cc < 8; cc++) {
        const int s0 = cc * 32;
        float sacc[2][4][4] = {};

        #pragma unroll
        for (int ni = 0; ni < 4; ni++) {
            uint32_t kb[2];
            ldm_x2(kb, sK + 2*((s0 + ni*8 + (lane & 7))*24 + ((lane >> 3) & 1)*8));
            #pragma unroll
            for (int mi = 0; mi < 2; mi++)
                mma16(sacc[mi][ni], qa[mi], kb);
        }

        // bias + exp + row-sum (bounded scores: no running max)
        #pragma unroll
        for (int mi = 0; mi < 2; mi++)
            #pragma unroll
            for (int ni = 0; ni < 4; ni++) {
                int scol = s0 + ni*8 + 2*tig;
                int r0   = m0 + mi*16 + g;
                float p0 = __expf(sacc[mi][ni][0] + bs[r0     - scol     + (MAXT-1)]);
                float p1 = __expf(sacc[mi][ni][1] + bs[r0     - scol - 1 + (MAXT-1)]);
                float p2 = __expf(sacc[mi][ni][2] + bs[r0 + 8 - scol     + (MAXT-1)]);
                float p3 = __expf(sacc[mi][ni][3] + bs[r0 + 8 - scol - 1 + (MAXT-1)]);
                sacc[mi][ni][0] = p0; sacc[mi][ni][1] = p1;
                sacc[mi][ni][2] = p2; sacc[mi][ni][3] = p3;
                lsum[mi][0] += p0 + p1;
                lsum[mi][1] += p2 + p3;
            }

        // O += P @ V : C-fragment packs directly into bf16 A-fragment layout
        #pragma unroll
        for (int kk = 0; kk < 2; kk++) {
            uint32_t pa[2][4];
            #pragma unroll
            for (int mi = 0; mi < 2; mi++) {
                pa[mi][0] = packbf(sacc[mi][2*kk  ][0], sacc[mi][2*kk  ][1]);
                pa[mi][1] = packbf(sacc[mi][2*kk  ][2], sacc[mi][2*kk  ][3]);
                pa[mi][2] = packbf(sacc[mi][2*kk+1][0], sacc[mi][2*kk+1][1]);
                pa[mi][3] = packbf(sacc[mi][2*kk+1][2], sacc[mi][2*kk+1][3]);
            }
            #pragma unroll
            for (int nd = 0; nd < 2; nd++) {
                uint32_t vb[2];
                ldm_x2_t(vb, sV + 2*((s0 + kk*16 + (lane & 15))*24 + nd*8));
                #pragma unroll
                for (int mi = 0; mi < 2; mi++)
                    mma16(oacc[mi][nd], pa[mi], vb);
            }
        }
    }

    // reduce l across the 4 lanes of each row, normalize, write bf16
    #pragma unroll
    for (int mi = 0; mi < 2; mi++)
        #pragma unroll
        for (int rr = 0; rr < 2; rr++) {
            float v = lsum[mi][rr];
            v += __shfl_xor_sync(0xffffffffu, v, 1);
            v += __shfl_xor_sync(0xffffffffu, v, 2);
            lsum[mi][rr] = 1.0f / v;
        }

    #pragma unroll
    for (int mi = 0; mi < 2; mi++) {
        #pragma unroll
        for (int rr = 0; rr < 2; rr++) {
            int row = m0 + mi*16 + rr*8 + g;
            float il = lsum[mi][rr];
            long oidx = ((long)h*NTOK + seq*TT + row) * HD;
            #pragma unroll
            for (int nd = 0; nd < 2; nd++) {
                *(uint32_t*)&out[oidx + nd*8 + 2*tig] =
                    packbf(oacc[mi][nd][rr*2+0]*il, oacc[mi][nd][rr*2+1]*il);
            }
        }
    }
}

// -------------------------------- launch ----------------------------------------
extern "C" void kernel_launch(void* const* d_in, const int* in_sizes, int n_in,
                              void* d_out, int out_size)
{
    const float* x     = (const float*)d_in[0];
    const float* ln1g  = (const float*)d_in[1];
    const float* ln1b  = (const float*)d_in[2];
    const float* qkvw  = (const float*)d_in[3];
    const float* qkvb  = (const float*)d_in[4];
    const float* projw = (const float*)d_in[5];
    const float* projb = (const float*)d_in[6];
    const float* ls    = (const float*)d_in[7];
    const float* rpb   = (const float*)d_in[8];
    const float* ln2g  = (const float*)d_in[9];
    const float* ln2b  = (const float*)d_in[10];
    const float* w1    = (const float*)d_in[11];
    const float* b1    = (const float*)d_in[12];
    const float* w2    = (const float*)d_in[13];
    const float* b2    = (const float*)d_in[14];
    float* out = (float*)d_out;

    bf16 *xn, *qkv, *attn, *z, *hb, *wbuf;
    float *xf;
    cudaGetSymbolAddress((void**)&xn,   g_xn);
    cudaGetSymbolAddress((void**)&qkv,  g_qkv);
    cudaGetSymbolAddress((void**)&attn, g_attn);
    cudaGetSymbolAddress((void**)&xf,   g_xf);
    cudaGetSymbolAddress((void**)&z,    g_z);
    cudaGetSymbolAddress((void**)&hb,   g_h);
    cudaGetSymbolAddress((void**)&wbuf, g_w);

    cudaFuncSetAttribute(mma_gemm<128, 384, 4, 0>, cudaFuncAttributeMaxDynamicSharedMemorySize, GEMM_SMEM);
    cudaFuncSetAttribute(mma_gemm<128, 128, 1, 1>, cudaFuncAttributeMaxDynamicSharedMemorySize, GEMM_SMEM);
    cudaFuncSetAttribute(mma_gemm<128, 512, 2, 0>, cudaFuncAttributeMaxDynamicSharedMemorySize, GEMM_SMEM);
    cudaFuncSetAttribute(mma_gemm<512, 128, 3, 0>, cudaFuncAttributeMaxDynamicSharedMemorySize, GEMM_SMEM);

    // 0) weights -> bf16
    wprep_kernel<<<(WTOTAL + 255)/256, 256>>>(qkvw, projw, w1, w2, wbuf);
    // 1) gather + LN1 -> bf16 (warp per row)
    ln1_kernel<<<NTOK/8, 256>>>(x, ln1g, ln1b, xn);
    // 2) QKV projection -> head-major bf16 q/k/v
    mma_gemm<128, 384, 4, 0><<<dim3(3, NTOK/BM), 256, GEMM_SMEM>>>(
        xn, wbuf + WOFF_QKV, qkvb, nullptr, nullptr, qkv, nullptr, nullptr);
    // 3) bf16 tensor-core attention
    attn_bf16_kernel<<<dim3(SEQS, HH), 256>>>(qkv, ls, rpb, attn);
    // 4) proj + residual -> xf (fp32), fused LN2 -> z (bf16)
    mma_gemm<128, 128, 1, 1><<<dim3(1, NTOK/BM), 256, GEMM_SMEM>>>(
        attn, wbuf + WOFF_PROJ, projb, x, xf, z, ln2g, ln2b);
    // 5) FFN1 + exact GELU -> h (bf16)
    mma_gemm<128, 512, 2, 0><<<dim3(4, NTOK/BM), 256, GEMM_SMEM>>>(
        z, wbuf + WOFF_W1, b1, nullptr, nullptr, hb, nullptr, nullptr);
    // 6) FFN2 + residual -> scatter fp32 (B,T,V,D) output
    mma_gemm<512, 128, 3, 0><<<dim3(1, NTOK/BM), 256, GEMM_SMEM>>>(
        hb, wbuf + WOFF_W2, b2, xf, out, nullptr, nullptr, nullptr);
}

// round 6
// speedup vs baseline: 5.3416x; 1.0304x over previous
#include <cuda_runtime.h>
#include <cuda_bf16.h>
#include <math.h>
#include <stdint.h>

// Problem constants
#define BB   16
#define TT   256
#define VV   25
#define DM   128
#define HH   8
#define HD   16
#define MAXT 300
#define SEQS (BB*VV)          // 400
#define NTOK (SEQS*TT)        // 102400
#define NBIAS (2*MAXT-1)      // 599
#define PART (HH*NTOK*HD)     // per q/k/v head-major part size (elements)
#define LOG2E 1.4426950408889634f

// GEMM tiling (bf16)
#define BM 128
#define BN 128
#define BK 32
#define NSTG 4
#define ASTR 40               // A row stride in halves
#define BSTR (BN + 8)         // 136 halves
#define SA (BM*ASTR)
#define SB (BK*BSTR)
#define STG (SA + SB)
#define GEMM_SMEM (NSTG*STG*2)  // 75776 bytes

// fused FFN smem layout (halves)
#define FZ_STR 136
#define FG_STR 520
#define FW_STR 136
#define OFF_Z 0                          // 128*136      = 17408
#define OFF_G (128*FZ_STR)               // 17408, size 128*520 = 66560
#define OFF_W (OFF_G + 128*FG_STR)       // 83968, size 2*64*136 = 17408
#define FFN_SMEM ((OFF_W + 2*64*FW_STR)*2)   // 202752 bytes

// weight-prep segment offsets (bf16 copies)
#define WOFF_QKV  0
#define WOFF_PROJ 49152
#define WOFF_W1   65536
#define WOFF_W2   131072
#define WTOTAL    196608

typedef __nv_bfloat16 bf16;

// ---------------- scratch (device globals; no runtime allocation) -------------
__device__ bf16  g_xn  [NTOK*DM];     // LN1 output
__device__ bf16  g_qkv [NTOK*3*DM];   // q/k/v, head-major [3][H][NTOK][16]
__device__ bf16  g_attn[NTOK*DM];     // attention output, head-major
__device__ float g_xf  [NTOK*DM];     // after proj + residual (fp32)
__device__ bf16  g_z   [NTOK*DM];     // LN2 output
__device__ bf16  g_w   [WTOTAL];      // bf16 weights

// ---------------- helpers ------------------------------------------------------
__device__ __forceinline__ uint32_t packbf(float lo, float hi) {
    uint32_t r;
    asm("cvt.rn.bf16x2.f32 %0, %1, %2;" : "=r"(r) : "f"(hi), "f"(lo));
    return r;
}
__device__ __forceinline__ float2 unpk(uint32_t u) {
    __nv_bfloat162 h = *reinterpret_cast<__nv_bfloat162*>(&u);
    return make_float2(__bfloat162float(h.x), __bfloat162float(h.y));
}
__device__ __forceinline__ float ex2(float x) {
    float r;
    asm("ex2.approx.ftz.f32 %0, %1;" : "=f"(r) : "f"(x));
    return r;
}
__device__ __forceinline__ void mma16(float* c, const uint32_t* a, const uint32_t* b) {
    asm volatile(
        "mma.sync.aligned.m16n8k16.row.col.f32.bf16.bf16.f32 "
        "{%0,%1,%2,%3}, {%4,%5,%6,%7}, {%8,%9}, {%0,%1,%2,%3};"
        : "+f"(c[0]), "+f"(c[1]), "+f"(c[2]), "+f"(c[3])
        : "r"(a[0]), "r"(a[1]), "r"(a[2]), "r"(a[3]), "r"(b[0]), "r"(b[1]));
}
__device__ __forceinline__ void ldm_x4(uint32_t* r, uint32_t addr) {
    asm volatile("ldmatrix.sync.aligned.m8n8.x4.shared.b16 {%0,%1,%2,%3}, [%4];"
        : "=r"(r[0]), "=r"(r[1]), "=r"(r[2]), "=r"(r[3]) : "r"(addr));
}
__device__ __forceinline__ void ldm_x2(uint32_t* r, uint32_t addr) {
    asm volatile("ldmatrix.sync.aligned.m8n8.x2.shared.b16 {%0,%1}, [%2];"
        : "=r"(r[0]), "=r"(r[1]) : "r"(addr));
}
__device__ __forceinline__ void ldm_x2_t(uint32_t* r, uint32_t addr) {
    asm volatile("ldmatrix.sync.aligned.m8n8.x2.trans.shared.b16 {%0,%1}, [%2];"
        : "=r"(r[0]), "=r"(r[1]) : "r"(addr));
}
__device__ __forceinline__ void cp16(uint32_t dst, const void* src) {
    asm volatile("cp.async.cg.shared.global [%0], [%1], 16;" :: "r"(dst), "l"(src));
}
__device__ __forceinline__ void cp_commit() {
    asm volatile("cp.async.commit_group;" ::: "memory");
}
template<int N>
__device__ __forceinline__ void cp_wait() {
    asm volatile("cp.async.wait_group %0;" :: "n"(N) : "memory");
}
__device__ __forceinline__ int gather_off(int row) {
    int seq = row / TT, t = row % TT;
    int b = seq / VV, v = seq % VV;
    return ((b*TT + t)*VV + v) * DM;
}

// ---------------- weight prep: fp32 -> bf16 -------------------------------------
__global__ void wprep_kernel(const float* __restrict__ qkvw,
                             const float* __restrict__ projw,
                             const float* __restrict__ w1,
                             const float* __restrict__ w2,
                             bf16* __restrict__ dst)
{
    int i = blockIdx.x * blockDim.x + threadIdx.x;
    if (i >= WTOTAL) return;
    float v;
    if      (i < WOFF_PROJ) v = qkvw[i];
    else if (i < WOFF_W1)   v = projw[i - WOFF_PROJ];
    else if (i < WOFF_W2)   v = w1[i - WOFF_W1];
    else                    v = w2[i - WOFF_W2];
    dst[i] = __float2bfloat16(v);
}

// ---------------- LN1: warp per row, gather, bf16 out ---------------------------
__global__ void ln1_kernel(const float* __restrict__ in,
                           const float* __restrict__ gw,
                           const float* __restrict__ bw,
                           bf16* __restrict__ out)
{
    int m    = (blockIdx.x * blockDim.x + threadIdx.x) >> 5;
    int lane = threadIdx.x & 31;
    int seq = m / TT, t = m % TT;
    int b = seq / VV, v = seq % VV;
    const float* src = in + ((b*TT + t)*VV + v) * DM;

    float4 x = *(const float4*)(src + lane*4);
    float s = x.x + x.y + x.z + x.w;
    #pragma unroll
    for (int o = 16; o > 0; o >>= 1) s += __shfl_xor_sync(0xffffffffu, s, o);
    float mean = s * (1.0f / DM);

    float dx0 = x.x - mean, dx1 = x.y - mean, dx2 = x.z - mean, dx3 = x.w - mean;
    float q = dx0*dx0 + dx1*dx1 + dx2*dx2 + dx3*dx3;
    #pragma unroll
    for (int o = 16; o > 0; o >>= 1) q += __shfl_xor_sync(0xffffffffu, q, o);
    float inv = rsqrtf(q * (1.0f / DM) + 1e-5f);

    float4 gv = *(const float4*)(gw + lane*4);
    float4 bv = *(const float4*)(bw + lane*4);
    uint2 r;
    r.x = packbf(dx0*inv*gv.x + bv.x, dx1*inv*gv.y + bv.y);
    r.y = packbf(dx2*inv*gv.z + bv.z, dx3*inv*gv.w + bv.w);
    *(uint2*)(out + (long)m*DM + lane*4) = r;
}

// ---------------- bf16 tensor-core GEMM (QKV / proj+LN2) ------------------------
// EPI 1: + bias + gather(x) -> xf (Cf fp32); fused LayerNorm -> z (Cb bf16)
// EPI 4: + bias -> scatter head-major q/k/v (Cb)
// AG 1: A is head-major [H][NTOK][16] bf16
template<int KDIM, int NDIM, int EPI, int AG>
__global__ void __launch_bounds__(256, 2)
mma_gemm(const bf16* __restrict__ A,
         const bf16* __restrict__ B,
         const float* __restrict__ bias,
         const float* __restrict__ extra,
         float* __restrict__ Cf,
         bf16* __restrict__ Cb,
         const float* __restrict__ lng,
         const float* __restrict__ lnb)
{
    extern __shared__ bf16 smem[];
    uint32_t sbase = (uint32_t)__cvta_generic_to_shared(smem);

    const int tid  = threadIdx.x;
    const int bx   = blockIdx.x, by = blockIdx.y;
    const int lane = tid & 31, warp = tid >> 5;
    const int wm   = (warp & 1) * 64;
    const int wn   = (warp >> 1) * 32;
    const int g    = lane >> 2, tig = lane & 3;

    const int NK = KDIM / BK;
    float acc[4][4][4] = {};

    auto load_tile = [&](int kt, int slot) {
        uint32_t sb = sbase + 2*(slot*STG);
        #pragma unroll
        for (int i = 0; i < 2; i++) {
            int id = tid + i*256;
            int r = id >> 2, c8 = (id & 3) * 8;
            uint32_t dst = sb + 2*(r*ASTR + c8);
            int row = by*BM + r;
            if (AG) {
                int k = kt*BK + c8;
                cp16(dst, A + ((long)((k >> 4)*NTOK + row))*HD + (k & 15));
            } else {
                cp16(dst, A + (long)row*KDIM + kt*BK + c8);
            }
        }
        #pragma unroll
        for (int j = 0; j < 2; j++) {
            int id = tid + j*256;
            int r = id >> 4, c8 = (id & 15) * 8;
            uint32_t dst = sb + 2*(SA + r*BSTR + c8);
            cp16(dst, B + (long)(kt*BK + r)*NDIM + bx*BN + c8);
        }
    };

    #pragma unroll
    for (int s = 0; s < NSTG-1; s++) {
        if (s < NK) load_tile(s, s);
        cp_commit();
    }

    const int a_roff = (lane & 7) + ((lane >> 3) & 1) * 8;
    const int a_coff = (lane >> 4) * 8;
    const int b_roff = lane & 15;

    #pragma unroll 1
    for (int kt = 0; kt < NK; kt++) {
        cp_wait<NSTG-2>();
        __syncthreads();
        int lt = kt + NSTG - 1;
        if (lt < NK) load_tile(lt, lt & (NSTG-1));
        cp_commit();

        uint32_t abase = sbase + 2*((kt & (NSTG-1))*STG);
        uint32_t bbase = abase + 2*SA;

        #pragma unroll
        for (int ks = 0; ks < 2; ks++) {
            uint32_t af[4][4], bf[4][2];
            #pragma unroll
            for (int mi = 0; mi < 4; mi++)
                ldm_x4(af[mi], abase + 2*((wm + mi*16 + a_roff)*ASTR + ks*16 + a_coff));
            #pragma unroll
            for (int ni = 0; ni < 4; ni++)
                ldm_x2_t(bf[ni], bbase + 2*((ks*16 + b_roff)*BSTR + wn + ni*8));
            #pragma unroll
            for (int mi = 0; mi < 4; mi++)
                #pragma unroll
                for (int ni = 0; ni < 4; ni++)
                    mma16(acc[mi][ni], af[mi], bf[ni]);
        }
    }

    // ---------------- epilogue ----------------
    if (EPI == 1) {
        __syncthreads();
        float* red = (float*)smem;
        const int wngrp = warp >> 1;

        float rsum[4][2], rsq[4][2];
        #pragma unroll
        for (int mi = 0; mi < 4; mi++) {
            #pragma unroll
            for (int rr = 0; rr < 2; rr++) {
                int rloc = wm + mi*16 + rr*8 + g;
                int row  = by*BM + rloc;
                int go   = gather_off(row);
                float ls = 0.f, lq = 0.f;
                #pragma unroll
                for (int ni = 0; ni < 4; ni++) {
                    int col = wn + ni*8 + 2*tig;
                    float vx = acc[mi][ni][rr*2+0] + bias[col]   + extra[go + col];
                    float vy = acc[mi][ni][rr*2+1] + bias[col+1] + extra[go + col + 1];
                    acc[mi][ni][rr*2+0] = vx;
                    acc[mi][ni][rr*2+1] = vy;
                    float2 r = {vx, vy};
                    *(float2*)&Cf[(long)row*DM + col] = r;
                    ls += vx + vy;
                    lq += vx*vx + vy*vy;
                }
                rsum[mi][rr] = ls; rsq[mi][rr] = lq;
            }
        }
        #pragma unroll
        for (int mi = 0; mi < 4; mi++)
            #pragma unroll
            for (int rr = 0; rr < 2; rr++) {
                #pragma unroll
                for (int o = 1; o <= 2; o <<= 1) {
                    rsum[mi][rr] += __shfl_xor_sync(0xffffffffu, rsum[mi][rr], o);
                    rsq[mi][rr]  += __shfl_xor_sync(0xffffffffu, rsq[mi][rr],  o);
                }
            }
        if (tig == 0) {
            #pragma unroll
            for (int mi = 0; mi < 4; mi++)
                #pragma unroll
                for (int rr = 0; rr < 2; rr++) {
                    int rloc = wm + mi*16 + rr*8 + g;
                    red[(rloc*4 + wngrp)*2 + 0] = rsum[mi][rr];
                    red[(rloc*4 + wngrp)*2 + 1] = rsq[mi][rr];
                }
        }
        __syncthreads();
        #pragma unroll
        for (int mi = 0; mi < 4; mi++) {
            #pragma unroll
            for (int rr = 0; rr < 2; rr++) {
                int rloc = wm + mi*16 + rr*8 + g;
                int row  = by*BM + rloc;
                float s = 0.f, q = 0.f;
                #pragma unroll
                for (int w2 = 0; w2 < 4; w2++) {
                    s += red[(rloc*4 + w2)*2 + 0];
                    q += red[(rloc*4 + w2)*2 + 1];
                }
                float mean = s * (1.0f/DM);
                float var  = q * (1.0f/DM) - mean*mean;
                float inv  = rsqrtf(var + 1e-5f);
                #pragma unroll
                for (int ni = 0; ni < 4; ni++) {
                    int col = wn + ni*8 + 2*tig;
                    float zx = (acc[mi][ni][rr*2+0] - mean)*inv*lng[col]   + lnb[col];
                    float zy = (acc[mi][ni][rr*2+1] - mean)*inv*lng[col+1] + lnb[col+1];
                    *(uint32_t*)&Cb[(long)row*DM + col] = packbf(zx, zy);
                }
            }
        }
        return;
    }

    // EPI 4: head-major q/k/v scatter
    #pragma unroll
    for (int mi = 0; mi < 4; mi++) {
        #pragma unroll
        for (int rr = 0; rr < 2; rr++) {
            int row = by*BM + wm + mi*16 + rr*8 + g;
            #pragma unroll
            for (int ni = 0; ni < 4; ni++) {
                int col = bx*BN + wn + ni*8 + 2*tig;
                float vx = acc[mi][ni][rr*2 + 0] + bias[col];
                float vy = acc[mi][ni][rr*2 + 1] + bias[col + 1];
                int part = col >> 7, rem = col & 127;
                int hh = rem >> 4, d = rem & 15;
                *(uint32_t*)&Cb[(long)part*PART + ((long)hh*NTOK + row)*HD + d] =
                    packbf(vx, vy);
            }
        }
    }
}

// ---------------- fused FFN: out = scatter(gelu(z@W1+b1)@W2 + b2 + xf) ----------
__global__ void __launch_bounds__(256, 1)
ffn_fused(const bf16* __restrict__ z,
          const bf16* __restrict__ w1,
          const float* __restrict__ b1,
          const bf16* __restrict__ w2,
          const float* __restrict__ b2,
          const float* __restrict__ xf,
          float* __restrict__ out)
{
    extern __shared__ bf16 sm[];
    uint32_t sb = (uint32_t)__cvta_generic_to_shared(sm);

    const int tid  = threadIdx.x;
    const int by   = blockIdx.x;
    const int lane = tid & 31, warp = tid >> 5;
    const int wm   = (warp & 1) * 64;
    const int wn   = (warp >> 1) * 32;
    const int g    = lane >> 2, tig = lane & 3;

    const int a_roff = (lane & 7) + ((lane >> 3) & 1) * 8;
    const int a_coff = (lane >> 4) * 8;
    const int b_roff = lane & 15;

    // ---- prologue: Z tile (128x128) + W1 chunk 0, one commit group ----
    #pragma unroll
    for (int i = 0; i < 8; i++) {
        int id = tid + i*256;
        int r = id >> 4, c8 = (id & 15) * 8;
        cp16(sb + 2*(OFF_Z + r*FZ_STR + c8), z + (long)(by*BM + r)*DM + c8);
    }
    auto loadW1 = [&](int ii, int slot) {   // ii = nc*2+kc
        int nc = ii >> 1, kc = ii & 1;
        #pragma unroll
        for (int j = 0; j < 4; j++) {
            int id = tid + j*256;
            int r = id >> 4, c8 = (id & 15) * 8;
            cp16(sb + 2*(OFF_W + slot*64*FW_STR + r*FW_STR + c8),
                 w1 + (long)(kc*64 + r)*512 + nc*128 + c8);
        }
    };
    auto loadW2 = [&](int kc2, int slot) {
        #pragma unroll
        for (int j = 0; j < 4; j++) {
            int id = tid + j*256;
            int r = id >> 4, c8 = (id & 15) * 8;
            cp16(sb + 2*(OFF_W + slot*64*FW_STR + r*FW_STR + c8),
                 w2 + (long)(kc2*64 + r)*DM + c8);
        }
    };
    loadW1(0, 0);
    cp_commit();

    // ---- stage A: G = gelu(z@W1 + b1), 4 column-chunks of 128 -------------
    float acc[4][4][4];
    #pragma unroll 1
    for (int i = 0; i < 8; i++) {          // nc = i>>1, kc = i&1
        if (i < 7) loadW1(i + 1, (i + 1) & 1);
        else       loadW2(0, 0);
        cp_commit();
        cp_wait<1>();
        __syncthreads();

        const int nc = i >> 1, kc = i & 1, slot = i & 1;
        if (kc == 0) {
            #pragma unroll
            for (int mi = 0; mi < 4; mi++)
                #pragma unroll
                for (int ni = 0; ni < 4; ni++)
                    #pragma unroll
                    for (int e = 0; e < 4; e++) acc[mi][ni][e] = 0.f;
        }
        #pragma unroll
        for (int ks = 0; ks < 4; ks++) {
            uint32_t af[4][4], bf[4][2];
            #pragma unroll
            for (int mi = 0; mi < 4; mi++)
                ldm_x4(af[mi], sb + 2*(OFF_Z + (wm + mi*16 + a_roff)*FZ_STR
                                        + kc*64 + ks*16 + a_coff));
            #pragma unroll
            for (int ni = 0; ni < 4; ni++)
                ldm_x2_t(bf[ni], sb + 2*(OFF_W + slot*64*FW_STR
                                        + (ks*16 + b_roff)*FW_STR + wn + ni*8));
            #pragma unroll
            for (int mi = 0; mi < 4; mi++)
                #pragma unroll
                for (int ni = 0; ni < 4; ni++)
                    mma16(acc[mi][ni], af[mi], bf[ni]);
        }
        if (kc == 1) {
            // gelu + pack into Gs
            #pragma unroll
            for (int mi = 0; mi < 4; mi++)
                #pragma unroll
                for (int rr = 0; rr < 2; rr++) {
                    int rloc = wm + mi*16 + rr*8 + g;
                    #pragma unroll
                    for (int ni = 0; ni < 4; ni++) {
                        int cl = wn + ni*8 + 2*tig;
                        float vx = acc[mi][ni][rr*2+0] + b1[nc*128 + cl];
                        float vy = acc[mi][ni][rr*2+1] + b1[nc*128 + cl + 1];
                        vx = 0.5f * vx * (1.0f + erff(vx * 0.70710678118654752f));
                        vy = 0.5f * vy * (1.0f + erff(vy * 0.70710678118654752f));
                        *(uint32_t*)&sm[OFF_G + rloc*FG_STR + nc*128 + cl] =
                            packbf(vx, vy);
                    }
                }
        }
        __syncthreads();
    }

    // ---- stage B: out = G@W2 + b2 + xf, K=512 in 8 chunks of 64 -----------
    float acc2[4][4][4] = {};
    #pragma unroll 1
    for (int i2 = 0; i2 < 8; i2++) {
        if (i2 < 7) { loadW2(i2 + 1, (i2 + 1) & 1); cp_commit(); cp_wait<1>(); }
        else        { cp_wait<0>(); }
        __syncthreads();

        const int slot = i2 & 1;
        #pragma unroll
        for (int ks = 0; ks < 4; ks++) {
            uint32_t af[4][4], bf[4][2];
            #pragma unroll
            for (int mi = 0; mi < 4; mi++)
                ldm_x4(af[mi], sb + 2*(OFF_G + (wm + mi*16 + a_roff)*FG_STR
                                        + i2*64 + ks*16 + a_coff));
            #pragma unroll
            for (int ni = 0; ni < 4; ni++)
                ldm_x2_t(bf[ni], sb + 2*(OFF_W + slot*64*FW_STR
                                        + (ks*16 + b_roff)*FW_STR + wn + ni*8));
            #pragma unroll
            for (int mi = 0; mi < 4; mi++)
                #pragma unroll
                for (int ni = 0; ni < 4; ni++)
                    mma16(acc2[mi][ni], af[mi], bf[ni]);
        }
        __syncthreads();
    }

    // epilogue: + b2 + xf, scatter to (B,T,V,D)
    #pragma unroll
    for (int mi = 0; mi < 4; mi++) {
        #pragma unroll
        for (int rr = 0; rr < 2; rr++) {
            int row = by*BM + wm + mi*16 + rr*8 + g;
            int go  = gather_off(row);
            #pragma unroll
            for (int ni = 0; ni < 4; ni++) {
                int col = wn + ni*8 + 2*tig;
                float vx = acc2[mi][ni][rr*2+0] + b2[col]   + xf[(long)row*DM + col];
                float vy = acc2[mi][ni][rr*2+1] + b2[col+1] + xf[(long)row*DM + col + 1];
                float2 r = {vx, vy};
                *(float2*)&out[go + col] = r;
            }
        }
    }
}

// ---------------- bf16 tensor-core attention ------------------------------------
// log2-domain exp (ex2), bias preloaded into accumulator, row-sums via V ones-col.
__global__ void __launch_bounds__(256)
attn_bf16_kernel(const bf16* __restrict__ qkv,
                 const float* __restrict__ logit_scale,
                 const float* __restrict__ rpb,
                 bf16* __restrict__ out)
{
    __shared__ __align__(16) bf16 Qs[TT*24];
    __shared__ __align__(16) bf16 Ks[TT*24];
    __shared__ __align__(16) bf16 Vs[TT*24];
    __shared__ float bs[NBIAS + 1];

    const int seq = blockIdx.x, h = blockIdx.y;
    const int t    = threadIdx.x;
    const int lane = t & 31, w = t >> 5;
    const int g    = lane >> 2, tig = lane & 3;

    for (int i = t; i < NBIAS; i += 256) bs[i] = rpb[h*NBIAS + i] * LOG2E;

    const long idx = ((long)h*NTOK + seq*TT + t) * HD;
    const float scale = __expf(fminf(logit_scale[h], 4.6051701859880914f));

    {   // load one q/k/v row per thread; q scaled by log2e too
        uint4 qu0 = *(const uint4*)(qkv + idx);
        uint4 qu1 = *(const uint4*)(qkv + idx + 8);
        uint4 ku0 = *(const uint4*)(qkv + PART + idx);
        uint4 ku1 = *(const uint4*)(qkv + PART + idx + 8);
        uint4 vu0 = *(const uint4*)(qkv + 2L*PART + idx);
        uint4 vu1 = *(const uint4*)(qkv + 2L*PART + idx + 8);

        uint32_t uq[8] = {qu0.x,qu0.y,qu0.z,qu0.w, qu1.x,qu1.y,qu1.z,qu1.w};
        uint32_t uk[8] = {ku0.x,ku0.y,ku0.z,ku0.w, ku1.x,ku1.y,ku1.z,ku1.w};
        float q[16], k[16];
        float qs = 0.f, ks = 0.f;
        #pragma unroll
        for (int j = 0; j < 8; j++) {
            float2 fq = unpk(uq[j]), fk = unpk(uk[j]);
            q[2*j] = fq.x; q[2*j+1] = fq.y;
            k[2*j] = fk.x; k[2*j+1] = fk.y;
            qs += fq.x*fq.x + fq.y*fq.y;
            ks += fk.x*fk.x + fk.y*fk.y;
        }
        float qf = scale * 0.25f * LOG2E / fmaxf(sqrtf(qs), 1e-12f);
        float kf = 1.0f / fmaxf(sqrtf(ks), 1e-12f);
        uint32_t wq[8], wk[8];
        #pragma unroll
        for (int j = 0; j < 8; j++) {
            wq[j] = packbf(q[2*j]*qf, q[2*j+1]*qf);
            wk[j] = packbf(k[2*j]*kf, k[2*j+1]*kf);
        }
        *(uint4*)&Qs[t*24]     = make_uint4(wq[0],wq[1],wq[2],wq[3]);
        *(uint4*)&Qs[t*24 + 8] = make_uint4(wq[4],wq[5],wq[6],wq[7]);
        *(uint4*)&Ks[t*24]     = make_uint4(wk[0],wk[1],wk[2],wk[3]);
        *(uint4*)&Ks[t*24 + 8] = make_uint4(wk[4],wk[5],wk[6],wk[7]);
        *(uint4*)&Vs[t*24]      = vu0;
        *(uint4*)&Vs[t*24 + 8]  = vu1;
        // cols 16..23: ones column (col16=1.0bf16) for row-sum MMA
        *(uint4*)&Vs[t*24 + 16] = make_uint4(0x00003F80u, 0u, 0u, 0u);
    }
    __syncthreads();

    uint32_t sQ = (uint32_t)__cvta_generic_to_shared(Qs);
    uint32_t sK = (uint32_t)__cvta_generic_to_shared(Ks);
    uint32_t sV = (uint32_t)__cvta_generic_to_shared(Vs);

    const int m0 = w * 32;
    const int fr = (lane & 7) + ((lane >> 3) & 1) * 8;
    const int fc = (lane >> 4) * 8;

    uint32_t qa[2][4];
    #pragma unroll
    for (int mi = 0; mi < 2; mi++)
        ldm_x4(qa[mi], sQ + 2*((m0 + mi*16 + fr)*24 + fc));

    float oacc[2][3][4] = {};

    #pragma unroll 1
    for (int cc = 0; cc < 8; cc++) {
        const int s0 = cc * 32;
        float sacc[2][4][4];

        // init accumulator with (log2-scaled) bias
        #pragma unroll
        for (int mi = 0; mi < 2; mi++)
            #pragma unroll
            for (int ni = 0; ni < 4; ni++) {
                int d = m0 + mi*16 + g - (s0 + ni*8 + 2*tig) + (MAXT-1);
                sacc[mi][ni][0] = bs[d];
                sacc[mi][ni][1] = bs[d-1];
                sacc[mi][ni][2] = bs[d+8];
                sacc[mi][ni][3] = bs[d+7];
            }

        #pragma unroll
        for (int ni = 0; ni < 4; ni++) {
            uint32_t kb[2];
            ldm_x2(kb, sK + 2*((s0 + ni*8 + (lane & 7))*24 + ((lane >> 3) & 1)*8));
            #pragma unroll
            for (int mi = 0; mi < 2; mi++)
                mma16(sacc[mi][ni], qa[mi], kb);
        }

        // exp2 (scores bounded; no running max)
        #pragma unroll
        for (int mi = 0; mi < 2; mi++)
            #pragma unroll
            for (int ni = 0; ni < 4; ni++) {
                sacc[mi][ni][0] = ex2(sacc[mi][ni][0]);
                sacc[mi][ni][1] = ex2(sacc[mi][ni][1]);
                sacc[mi][ni][2] = ex2(sacc[mi][ni][2]);
                sacc[mi][ni][3] = ex2(sacc[mi][ni][3]);
            }

        // O += P @ [V | ones]: C-fragment packs directly into bf16 A-fragment
        #pragma unroll
        for (int kk = 0; kk < 2; kk++) {
            uint32_t pa[2][4];
            #pragma unroll
            for (int mi = 0; mi < 2; mi++) {
                pa[mi][0] = packbf(sacc[mi][2*kk  ][0], sacc[mi][2*kk  ][1]);
                pa[mi][1] = packbf(sacc[mi][2*kk  ][2], sacc[mi][2*kk  ][3]);
                pa[mi][2] = packbf(sacc[mi][2*kk+1][0], sacc[mi][2*kk+1][1]);
                pa[mi][3] = packbf(sacc[mi][2*kk+1][2], sacc[mi][2*kk+1][3]);
            }
            #pragma unroll
            for (int nd = 0; nd < 3; nd++) {
                uint32_t vb[2];
                ldm_x2_t(vb, sV + 2*((s0 + kk*16 + (lane & 15))*24 + nd*8));
                #pragma unroll
                for (int mi = 0; mi < 2; mi++)
                    mma16(oacc[mi][nd], pa[mi], vb);
            }
        }
    }

    // l = ones-column sums (held by tig==0, col 16) -> broadcast, normalize
    #pragma unroll
    for (int mi = 0; mi < 2; mi++) {
        #pragma unroll
        for (int rr = 0; rr < 2; rr++) {
            float l = __shfl_sync(0xffffffffu, oacc[mi][2][rr*2], lane & ~3);
            float il = 1.0f / l;
            int row = m0 + mi*16 + rr*8 + g;
            long oidx = ((long)h*NTOK + seq*TT + row) * HD;
            #pragma unroll
            for (int nd = 0; nd < 2; nd++) {
                *(uint32_t*)&out[oidx + nd*8 + 2*tig] =
                    packbf(oacc[mi][nd][rr*2+0]*il, oacc[mi][nd][rr*2+1]*il);
            }
        }
    }
}

// -------------------------------- launch ----------------------------------------
extern "C" void kernel_launch(void* const* d_in, const int* in_sizes, int n_in,
                              void* d_out, int out_size)
{
    const float* x     = (const float*)d_in[0];
    const float* ln1g  = (const float*)d_in[1];
    const float* ln1b  = (const float*)d_in[2];
    const float* qkvw  = (const float*)d_in[3];
    const float* qkvb  = (const float*)d_in[4];
    const float* projw = (const float*)d_in[5];
    const float* projb = (const float*)d_in[6];
    const float* ls    = (const float*)d_in[7];
    const float* rpb   = (const float*)d_in[8];
    const float* ln2g  = (const float*)d_in[9];
    const float* ln2b  = (const float*)d_in[10];
    const float* w1    = (const float*)d_in[11];
    const float* b1    = (const float*)d_in[12];
    const float* w2    = (const float*)d_in[13];
    const float* b2    = (const float*)d_in[14];
    float* out = (float*)d_out;

    bf16 *xn, *qkv, *attn, *z, *wbuf;
    float *xf;
    cudaGetSymbolAddress((void**)&xn,   g_xn);
    cudaGetSymbolAddress((void**)&qkv,  g_qkv);
    cudaGetSymbolAddress((void**)&attn, g_attn);
    cudaGetSymbolAddress((void**)&xf,   g_xf);
    cudaGetSymbolAddress((void**)&z,    g_z);
    cudaGetSymbolAddress((void**)&wbuf, g_w);

    cudaFuncSetAttribute(mma_gemm<128, 384, 4, 0>, cudaFuncAttributeMaxDynamicSharedMemorySize, GEMM_SMEM);
    cudaFuncSetAttribute(mma_gemm<128, 128, 1, 1>, cudaFuncAttributeMaxDynamicSharedMemorySize, GEMM_SMEM);
    cudaFuncSetAttribute(ffn_fused, cudaFuncAttributeMaxDynamicSharedMemorySize, FFN_SMEM);

    // 0) weights -> bf16
    wprep_kernel<<<(WTOTAL + 255)/256, 256>>>(qkvw, projw, w1, w2, wbuf);
    // 1) gather + LN1 -> bf16
    ln1_kernel<<<NTOK/8, 256>>>(x, ln1g, ln1b, xn);
    // 2) QKV projection -> head-major bf16 q/k/v
    mma_gemm<128, 384, 4, 0><<<dim3(3, NTOK/BM), 256, GEMM_SMEM>>>(
        xn, wbuf + WOFF_QKV, qkvb, nullptr, nullptr, qkv, nullptr, nullptr);
    // 3) bf16 tensor-core attention
    attn_bf16_kernel<<<dim3(SEQS, HH), 256>>>(qkv, ls, rpb, attn);
    // 4) proj + residual -> xf (fp32), fused LN2 -> z (bf16)
    mma_gemm<128, 128, 1, 1><<<dim3(1, NTOK/BM), 256, GEMM_SMEM>>>(
        attn, wbuf + WOFF_PROJ, projb, x, xf, z, ln2g, ln2b);
    // 5+6) fused FFN1 + GELU + FFN2 + residual -> scatter fp32 output
    ffn_fused<<<NTOK/BM, 256, FFN_SMEM>>>(
        z, wbuf + WOFF_W1, b1, wbuf + WOFF_W2, b2, xf, out);
}